// round 7
// baseline (speedup 1.0000x reference)
#include <cuda_runtime.h>
#include <math.h>

// ---------------- problem constants ----------------
#define Dm      1024
#define Hh      16
#define DHd     64
#define Ff      4096
#define Ee      8
#define TOPK    2
#define Bbat    2
#define Sseq    2048
#define Ntok    4096
#define NKCAP   16384

// GEMM tiling: 128x128x32 tile, 128 threads (4 warps of 64x64)
#define AP 36
#define BP 136
#define GEMM_ASZ (128 * AP)
#define GEMM_BSZ (32 * BP)
#define GEMM_STG (GEMM_ASZ + GEMM_BSZ)
#define GEMM_NSTAGE 3
#define GEMM_SMEM (GEMM_NSTAGE * GEMM_STG * 4)

// flash tiling (register-staged, proven)
#define QT      128
#define KC      64
#define KSP     68
#define VSP     72
#define PSP     68
#define FLASH_SMEM ((KC*KSP + KC*VSP + QT*PSP) * 4)

// ---------------- device scratch ----------------
__device__ float g_Q [Ntok * Dm];
__device__ float g_K [Ntok * Dm];
__device__ float g_V [Ntok * Dm];
__device__ float g_AT[Ntok * Dm];
__device__ float g_PR[Ntok * Dm];
__device__ float g_X1[Ntok * Dm];
__device__ float g_X2[Ntok * Dm];

__device__ float g_XG[(size_t)NKCAP * Dm];
__device__ float g_HB[(size_t)NKCAP * Ff];
__device__ float g_YG[(size_t)NKCAP * Dm];

__device__ int   g_tok_e[Ntok * TOPK];
__device__ float g_tok_g[Ntok * TOPK];
__device__ int   g_tok_pos[Ntok * TOPK];
__device__ int   g_cnt[Ee];
__device__ int   g_cur[Ee];
__device__ int   g_off[Ee + 1];
__device__ float g_auxp[Ntok * Ee];
__device__ int   g_auxi[Ntok * TOPK];

// ---------------- helpers ----------------
__device__ __forceinline__ unsigned f2tf(float f) {
    unsigned r;
    asm("cvt.rna.tf32.f32 %0, %1;" : "=r"(r) : "f"(f));
    return r;
}

__device__ __forceinline__ void mma_tf32(float* c, const unsigned* a, const unsigned* b) {
    asm volatile(
        "mma.sync.aligned.m16n8k8.row.col.f32.tf32.tf32.f32 "
        "{%0,%1,%2,%3},{%4,%5,%6,%7},{%8,%9},{%0,%1,%2,%3};\n"
        : "+f"(c[0]), "+f"(c[1]), "+f"(c[2]), "+f"(c[3])
        : "r"(a[0]), "r"(a[1]), "r"(a[2]), "r"(a[3]), "r"(b[0]), "r"(b[1]));
}

__device__ __forceinline__ void cp16(float* smem, const float* gmem, bool pred) {
    unsigned saddr = (unsigned)__cvta_generic_to_shared(smem);
    int sz = pred ? 16 : 0;
    asm volatile("cp.async.ca.shared.global [%0], [%1], 16, %2;\n"
                 :: "r"(saddr), "l"(gmem), "r"(sz));
}
__device__ __forceinline__ void cp_commit() {
    asm volatile("cp.async.commit_group;\n");
}
__device__ __forceinline__ void cp_wait1() {
    asm volatile("cp.async.wait_group 1;\n" ::: "memory");
}

// ---------------- GEMM core: 128x128x32, 128 threads, warp tile 64x64 ----------------
__device__ __forceinline__ void gemm_stage(
    float* As, float* Bs,
    const float* __restrict__ A, int lda,
    const float* __restrict__ Bg, int ldb,
    int bm, int bn, int k0, int M, int tid)
{
#pragma unroll
    for (int i = 0; i < 8; i++) {
        int idx = tid + i * 128;
        int r = idx >> 3, c = (idx & 7) << 2;
        bool p = (bm + r) < M;
        const float* src = A + (size_t)(p ? (bm + r) : 0) * lda + k0 + c;
        cp16(&As[r * AP + c], src, p);
    }
#pragma unroll
    for (int i = 0; i < 8; i++) {
        int idx = tid + i * 128;
        int r = idx >> 5, c = (idx & 31) << 2;
        cp16(&Bs[r * BP + c], Bg + (size_t)(k0 + r) * ldb + bn + c, true);
    }
}

__device__ __forceinline__ void mma_gemm_tile(
    const float* __restrict__ A, int lda,
    const float* __restrict__ Bg, int ldb,
    const float* __restrict__ bias,
    float* __restrict__ C, int ldc,
    int M, int Kd, int bm, int bn, int relu)
{
    extern __shared__ float smp[];

    const int tid  = threadIdx.x;
    const int lane = tid & 31;
    const int wid  = tid >> 5;
    const int wm = (wid >> 1) * 64;
    const int wn = (wid & 1) * 64;
    const int g  = lane >> 2;
    const int tg = lane & 3;

    float acc[4][8][4];
#pragma unroll
    for (int i = 0; i < 4; i++)
#pragma unroll
        for (int j = 0; j < 8; j++)
#pragma unroll
            for (int q = 0; q < 4; q++) acc[i][j][q] = 0.f;

    const int ktiles = Kd / 32;

    gemm_stage(smp, smp + GEMM_ASZ, A, lda, Bg, ldb, bm, bn, 0, M, tid);
    cp_commit();
    gemm_stage(smp + GEMM_STG, smp + GEMM_STG + GEMM_ASZ, A, lda, Bg, ldb, bm, bn, 32, M, tid);
    cp_commit();

    for (int t = 0; t < ktiles; t++) {
        cp_wait1();
        __syncthreads();

        if (t + 2 < ktiles) {
            float* dst = smp + ((t + 2) % GEMM_NSTAGE) * GEMM_STG;
            gemm_stage(dst, dst + GEMM_ASZ, A, lda, Bg, ldb, bm, bn, (t + 2) * 32, M, tid);
        }
        cp_commit();

        const unsigned* As = (const unsigned*)(smp + (t % GEMM_NSTAGE) * GEMM_STG);
        const unsigned* Bs = As + GEMM_ASZ;

#pragma unroll
        for (int ks = 0; ks < 4; ks++) {
            const int k = ks * 8;
            unsigned af[4][4], bf[8][2];
#pragma unroll
            for (int mt = 0; mt < 4; mt++) {
                int mb = wm + mt * 16;
                af[mt][0] = As[(mb + g)     * AP + k + tg];
                af[mt][1] = As[(mb + g + 8) * AP + k + tg];
                af[mt][2] = As[(mb + g)     * AP + k + tg + 4];
                af[mt][3] = As[(mb + g + 8) * AP + k + tg + 4];
            }
#pragma unroll
            for (int nt = 0; nt < 8; nt++) {
                int nb = wn + nt * 8;
                bf[nt][0] = Bs[(k + tg)     * BP + nb + g];
                bf[nt][1] = Bs[(k + tg + 4) * BP + nb + g];
            }
#pragma unroll
            for (int mt = 0; mt < 4; mt++)
#pragma unroll
                for (int nt = 0; nt < 8; nt++)
                    mma_tf32(acc[mt][nt], af[mt], bf[nt]);
        }
    }

#pragma unroll
    for (int mt = 0; mt < 4; mt++) {
#pragma unroll
        for (int nt = 0; nt < 8; nt++) {
            int row0 = bm + wm + mt * 16 + g;
            int col  = bn + wn + nt * 8 + tg * 2;
            float b0 = bias ? bias[col]     : 0.f;
            float b1 = bias ? bias[col + 1] : 0.f;
            float v0 = acc[mt][nt][0] + b0;
            float v1 = acc[mt][nt][1] + b1;
            float v2 = acc[mt][nt][2] + b0;
            float v3 = acc[mt][nt][3] + b1;
            if (relu) {
                v0 = fmaxf(v0, 0.f); v1 = fmaxf(v1, 0.f);
                v2 = fmaxf(v2, 0.f); v3 = fmaxf(v3, 0.f);
            }
            if (row0 < M)     *(float2*)(C + (size_t)row0 * ldc + col)       = make_float2(v0, v1);
            if (row0 + 8 < M) *(float2*)(C + (size_t)(row0 + 8) * ldc + col) = make_float2(v2, v3);
        }
    }
}

__global__ void __launch_bounds__(128) k_gemm128(
    const float* __restrict__ A, int lda, const float* __restrict__ B, int ldb,
    const float* __restrict__ bias, float* __restrict__ C, int ldc, int M, int Kd, int relu)
{
    mma_gemm_tile(A, lda, B, ldb, bias, C, ldc, M, Kd,
                  blockIdx.x * 128, blockIdx.y * 128, relu);
}

// batched 3-way projection GEMM: z selects (A, B, bias, C)
struct Ptr3 {
    const float* a[3];
    const float* b[3];
    const float* bias[3];
    float* c[3];
};

__global__ void __launch_bounds__(128) k_gemm_batch3(Ptr3 p)
{
    int z = blockIdx.z;
    mma_gemm_tile(p.a[z], Dm, p.b[z], Dm, p.bias[z], p.c[z], Dm, Ntok, Dm,
                  blockIdx.x * 128, blockIdx.y * 128, 0);
}

__global__ void __launch_bounds__(128) k_moe_gemm_mma(
    const float* __restrict__ Abase, const float* __restrict__ Wbase,
    const float* __restrict__ bbase, float* __restrict__ Cbase, int Kd, int Nn, int relu)
{
    int e = blockIdx.z;
    int cnt = g_cnt[e];
    int bm = blockIdx.x * 128;
    if (bm >= cnt) return;
    int off = g_off[e];
    mma_gemm_tile(Abase + (size_t)off * Kd, Kd,
                  Wbase + (size_t)e * Kd * Nn, Nn,
                  bbase + (size_t)e * Nn,
                  Cbase + (size_t)off * Nn, Nn,
                  cnt, Kd, bm, blockIdx.y * 128, relu);
}

// ---------------- flash attention (register-staged, proven) ----------------
__global__ void __launch_bounds__(256) k_flash(
    const float* __restrict__ Qg, const float* __restrict__ Kg,
    const float* __restrict__ Vg, float* __restrict__ AT)
{
    extern __shared__ float sm[];
    unsigned* Ks = (unsigned*)sm;
    unsigned* Vs = Ks + KC * KSP;
    unsigned* Ps = Vs + KC * VSP;

    const int bh = blockIdx.y;
    const int b = bh >> 4, h = bh & 15;
    const int q0 = blockIdx.x * QT;
    const int tid = threadIdx.x;
    const int lane = tid & 31;
    const int wid = tid >> 5;
    const int g = lane >> 2;
    const int tg = lane & 3;
    const int wrow = wid * 16;

    const float* Qp = Qg + (size_t)b * Sseq * Dm + h * DHd;
    const float* Kp = Kg + (size_t)b * Sseq * Dm + h * DHd;
    const float* Vp = Vg + (size_t)b * Sseq * Dm + h * DHd;

    unsigned qf[8][4];
#pragma unroll
    for (int kt = 0; kt < 8; kt++) {
        int k = kt * 8;
        qf[kt][0] = f2tf(Qp[(size_t)(q0 + wrow + g)     * Dm + k + tg]);
        qf[kt][1] = f2tf(Qp[(size_t)(q0 + wrow + g + 8) * Dm + k + tg]);
        qf[kt][2] = f2tf(Qp[(size_t)(q0 + wrow + g)     * Dm + k + tg + 4]);
        qf[kt][3] = f2tf(Qp[(size_t)(q0 + wrow + g + 8) * Dm + k + tg + 4]);
    }

    float oacc[8][4];
#pragma unroll
    for (int i = 0; i < 8; i++)
#pragma unroll
        for (int j = 0; j < 4; j++) oacc[i][j] = 0.f;
    float m0 = -1e30f, m1 = -1e30f, l0 = 0.f, l1 = 0.f;

    for (int c = 0; c < Sseq / KC; c++) {
        int kc0 = c * KC;
#pragma unroll
        for (int i = 0; i < 4; i++) {
            int idx = tid + i * 256;
            int r = idx >> 4, cc = (idx & 15) << 2;
            float4 kv = *(const float4*)(Kp + (size_t)(kc0 + r) * Dm + cc);
            unsigned* p = &Ks[r * KSP + cc];
            p[0] = f2tf(kv.x); p[1] = f2tf(kv.y); p[2] = f2tf(kv.z); p[3] = f2tf(kv.w);
            float4 vv = *(const float4*)(Vp + (size_t)(kc0 + r) * Dm + cc);
            unsigned* q = &Vs[r * VSP + cc];
            q[0] = f2tf(vv.x); q[1] = f2tf(vv.y); q[2] = f2tf(vv.z); q[3] = f2tf(vv.w);
        }
        __syncthreads();

        float sacc[8][4];
#pragma unroll
        for (int i = 0; i < 8; i++)
#pragma unroll
            for (int j = 0; j < 4; j++) sacc[i][j] = 0.f;
#pragma unroll
        for (int kt = 0; kt < 8; kt++) {
            int k = kt * 8;
            unsigned bf[8][2];
#pragma unroll
            for (int nt = 0; nt < 8; nt++) {
                bf[nt][0] = Ks[(nt * 8 + g) * KSP + k + tg];
                bf[nt][1] = Ks[(nt * 8 + g) * KSP + k + tg + 4];
            }
#pragma unroll
            for (int nt = 0; nt < 8; nt++)
                mma_tf32(sacc[nt], qf[kt], bf[nt]);
        }

        float mx0 = -1e30f, mx1 = -1e30f;
#pragma unroll
        for (int nt = 0; nt < 8; nt++) {
            sacc[nt][0] *= 0.125f; sacc[nt][1] *= 0.125f;
            sacc[nt][2] *= 0.125f; sacc[nt][3] *= 0.125f;
            mx0 = fmaxf(mx0, fmaxf(sacc[nt][0], sacc[nt][1]));
            mx1 = fmaxf(mx1, fmaxf(sacc[nt][2], sacc[nt][3]));
        }
        mx0 = fmaxf(mx0, __shfl_xor_sync(0xffffffff, mx0, 1));
        mx0 = fmaxf(mx0, __shfl_xor_sync(0xffffffff, mx0, 2));
        mx1 = fmaxf(mx1, __shfl_xor_sync(0xffffffff, mx1, 1));
        mx1 = fmaxf(mx1, __shfl_xor_sync(0xffffffff, mx1, 2));
        float nm0 = fmaxf(m0, mx0), nm1 = fmaxf(m1, mx1);
        float sc0 = __expf(m0 - nm0), sc1 = __expf(m1 - nm1);
        float ps0 = 0.f, ps1 = 0.f;
#pragma unroll
        for (int nt = 0; nt < 8; nt++) {
            float p00 = __expf(sacc[nt][0] - nm0);
            float p01 = __expf(sacc[nt][1] - nm0);
            float p10 = __expf(sacc[nt][2] - nm1);
            float p11 = __expf(sacc[nt][3] - nm1);
            ps0 += p00 + p01; ps1 += p10 + p11;
            int col = nt * 8 + tg * 2;
            *(uint2*)&Ps[(wrow + g)     * PSP + col] = make_uint2(f2tf(p00), f2tf(p01));
            *(uint2*)&Ps[(wrow + g + 8) * PSP + col] = make_uint2(f2tf(p10), f2tf(p11));
        }
        ps0 += __shfl_xor_sync(0xffffffff, ps0, 1);
        ps0 += __shfl_xor_sync(0xffffffff, ps0, 2);
        ps1 += __shfl_xor_sync(0xffffffff, ps1, 1);
        ps1 += __shfl_xor_sync(0xffffffff, ps1, 2);
        l0 = l0 * sc0 + ps0; l1 = l1 * sc1 + ps1;
        m0 = nm0; m1 = nm1;
#pragma unroll
        for (int nt = 0; nt < 8; nt++) {
            oacc[nt][0] *= sc0; oacc[nt][1] *= sc0;
            oacc[nt][2] *= sc1; oacc[nt][3] *= sc1;
        }
        __syncwarp();

#pragma unroll
        for (int kt = 0; kt < 8; kt++) {
            int k = kt * 8;
            unsigned af[4];
            af[0] = Ps[(wrow + g)     * PSP + k + tg];
            af[1] = Ps[(wrow + g + 8) * PSP + k + tg];
            af[2] = Ps[(wrow + g)     * PSP + k + tg + 4];
            af[3] = Ps[(wrow + g + 8) * PSP + k + tg + 4];
            unsigned bf[8][2];
#pragma unroll
            for (int nt = 0; nt < 8; nt++) {
                bf[nt][0] = Vs[(k + tg)     * VSP + nt * 8 + g];
                bf[nt][1] = Vs[(k + tg + 4) * VSP + nt * 8 + g];
            }
#pragma unroll
            for (int nt = 0; nt < 8; nt++)
                mma_tf32(oacc[nt], af, bf[nt]);
        }
        __syncthreads();
    }

    float inv0 = 1.f / l0, inv1 = 1.f / l1;
    float* Op = AT + (size_t)b * Sseq * Dm + h * DHd;
#pragma unroll
    for (int nt = 0; nt < 8; nt++) {
        int col = nt * 8 + tg * 2;
        *(float2*)(Op + (size_t)(q0 + wrow + g) * Dm + col) =
            make_float2(oacc[nt][0] * inv0, oacc[nt][1] * inv0);
        *(float2*)(Op + (size_t)(q0 + wrow + g + 8) * Dm + col) =
            make_float2(oacc[nt][2] * inv1, oacc[nt][3] * inv1);
    }
}

// ---------------- layernorm(residual) ----------------
__global__ void k_ln_res(const float* __restrict__ X, const float* __restrict__ R,
                         const float* __restrict__ gw, const float* __restrict__ bw,
                         float* __restrict__ O)
{
    int t = blockIdx.x, tid = threadIdx.x;
    const float* xp = X + (size_t)t * Dm;
    const float* rp = R + (size_t)t * Dm;
    float v[4]; float s = 0.f;
#pragma unroll
    for (int i = 0; i < 4; i++) { int d = tid + i * 256; v[i] = xp[d] + rp[d]; s += v[i]; }
    __shared__ float red[256];
    red[tid] = s; __syncthreads();
    for (int st = 128; st > 0; st >>= 1) {
        if (tid < st) red[tid] += red[tid + st];
        __syncthreads();
    }
    float mean = red[0] * (1.f / Dm);
    __syncthreads();
    float s2 = 0.f;
#pragma unroll
    for (int i = 0; i < 4; i++) { float dd = v[i] - mean; s2 += dd * dd; }
    red[tid] = s2; __syncthreads();
    for (int st = 128; st > 0; st >>= 1) {
        if (tid < st) red[tid] += red[tid + st];
        __syncthreads();
    }
    float rstd = rsqrtf(red[0] * (1.f / Dm) + 1e-5f);
    float* op = O + (size_t)t * Dm;
#pragma unroll
    for (int i = 0; i < 4; i++) {
        int d = tid + i * 256;
        op[d] = (v[i] - mean) * rstd * gw[d] + bw[d];
    }
}

// ---------------- router math shared by fused kernels ----------------
__device__ __forceinline__ void router_block(
    const float v[4], int tid, int t,
    const float* __restrict__ rw, const float* __restrict__ rb,
    float* red8, int mode)
{
    float loc[Ee];
#pragma unroll
    for (int e = 0; e < Ee; e++) loc[e] = 0.f;
#pragma unroll
    for (int i = 0; i < 4; i++) {
        int d = tid + i * 256;
        float xv = v[i];
#pragma unroll
        for (int e = 0; e < Ee; e++) loc[e] += xv * rw[d * Ee + e];
    }
#pragma unroll
    for (int e = 0; e < Ee; e++) red8[tid * Ee + e] = loc[e];
    __syncthreads();
    for (int st = 128; st > 0; st >>= 1) {
        if (tid < st)
#pragma unroll
            for (int e = 0; e < Ee; e++)
                red8[tid * Ee + e] += red8[(tid + st) * Ee + e];
        __syncthreads();
    }
    if (tid == 0) {
        float lg[Ee], mx = -1e30f;
#pragma unroll
        for (int e = 0; e < Ee; e++) { lg[e] = red8[e] + rb[e]; mx = fmaxf(mx, lg[e]); }
        float sm = 0.f;
#pragma unroll
        for (int e = 0; e < Ee; e++) { lg[e] = expf(lg[e] - mx); sm += lg[e]; }
        float inv = 1.f / sm;
#pragma unroll
        for (int e = 0; e < Ee; e++) lg[e] *= inv;
        int e0 = 0;
#pragma unroll
        for (int e = 1; e < Ee; e++) if (lg[e] > lg[e0]) e0 = e;
        int e1 = -1;
#pragma unroll
        for (int e = 0; e < Ee; e++)
            if (e != e0 && (e1 < 0 || lg[e] > lg[e1])) e1 = e;
        if (mode == 0) {
            float g0 = lg[e0], g1 = lg[e1], gs = g0 + g1;
            g_tok_e[t * 2] = e0;  g_tok_e[t * 2 + 1] = e1;
            g_tok_g[t * 2] = g0 / gs; g_tok_g[t * 2 + 1] = g1 / gs;
            atomicAdd(&g_cnt[e0], 1); atomicAdd(&g_cnt[e1], 1);
        } else {
#pragma unroll
            for (int e = 0; e < Ee; e++) g_auxp[t * Ee + e] = lg[e];
            g_auxi[t * 2] = e0; g_auxi[t * 2 + 1] = e1;
        }
    }
}

// ---------------- fused ln2 + dispatch router ----------------
__global__ void k_ln_router(const float* __restrict__ X, const float* __restrict__ R,
                            const float* __restrict__ gw, const float* __restrict__ bw,
                            float* __restrict__ O,
                            const float* __restrict__ rw, const float* __restrict__ rb)
{
    int t = blockIdx.x, tid = threadIdx.x;
    const float* xp = X + (size_t)t * Dm;
    const float* rp = R + (size_t)t * Dm;
    float v[4]; float s = 0.f;
#pragma unroll
    for (int i = 0; i < 4; i++) { int d = tid + i * 256; v[i] = xp[d] + rp[d]; s += v[i]; }
    __shared__ float red8[256 * Ee];
    red8[tid] = s; __syncthreads();
    for (int st = 128; st > 0; st >>= 1) {
        if (tid < st) red8[tid] += red8[tid + st];
        __syncthreads();
    }
    float mean = red8[0] * (1.f / Dm);
    __syncthreads();
    float s2 = 0.f;
#pragma unroll
    for (int i = 0; i < 4; i++) { float dd = v[i] - mean; s2 += dd * dd; }
    red8[tid] = s2; __syncthreads();
    for (int st = 128; st > 0; st >>= 1) {
        if (tid < st) red8[tid] += red8[tid + st];
        __syncthreads();
    }
    float rstd = rsqrtf(red8[0] * (1.f / Dm) + 1e-5f);
    __syncthreads();
    float* op = O + (size_t)t * Dm;
#pragma unroll
    for (int i = 0; i < 4; i++) {
        int d = tid + i * 256;
        v[i] = (v[i] - mean) * rstd * gw[d] + bw[d];
        op[d] = v[i];
    }
    router_block(v, tid, t, rw, rb, red8, 0);
}

// ---------------- fused MoE combine + ln3 + aux router ----------------
__global__ void k_moe_out(const float* __restrict__ X2,
                          const float* __restrict__ gw, const float* __restrict__ bw,
                          float* __restrict__ O,
                          const float* __restrict__ rw, const float* __restrict__ rb)
{
    int t = blockIdx.x, tid = threadIdx.x;
    int p0 = g_tok_pos[t * 2], p1 = g_tok_pos[t * 2 + 1];
    float w0 = g_tok_g[t * 2], w1 = g_tok_g[t * 2 + 1];
    const float* xp = X2 + (size_t)t * Dm;
    const float* y0 = g_YG + (size_t)p0 * Dm;
    const float* y1 = g_YG + (size_t)p1 * Dm;
    float v[4]; float s = 0.f;
#pragma unroll
    for (int i = 0; i < 4; i++) {
        int d = tid + i * 256;
        v[i] = xp[d] + w0 * y0[d] + w1 * y1[d];
        s += v[i];
    }
    __shared__ float red8[256 * Ee];
    red8[tid] = s; __syncthreads();
    for (int st = 128; st > 0; st >>= 1) {
        if (tid < st) red8[tid] += red8[tid + st];
        __syncthreads();
    }
    float mean = red8[0] * (1.f / Dm);
    __syncthreads();
    float s2 = 0.f;
#pragma unroll
    for (int i = 0; i < 4; i++) { float dd = v[i] - mean; s2 += dd * dd; }
    red8[tid] = s2; __syncthreads();
    for (int st = 128; st > 0; st >>= 1) {
        if (tid < st) red8[tid] += red8[tid + st];
        __syncthreads();
    }
    float rstd = rsqrtf(red8[0] * (1.f / Dm) + 1e-5f);
    __syncthreads();
    float* op = O + (size_t)t * Dm;
#pragma unroll
    for (int i = 0; i < 4; i++) {
        int d = tid + i * 256;
        v[i] = (v[i] - mean) * rstd * gw[d] + bw[d];
        op[d] = v[i];
    }
    router_block(v, tid, t, rw, rb, red8, 1);
}

// ---------------- MoE dispatch ----------------
__global__ void k_moe_init()
{
    int tid = threadIdx.x;
    if (tid < Ee) { g_cnt[tid] = 0; g_cur[tid] = 0; }
}

__global__ void k_offsets()
{
    if (threadIdx.x == 0) {
        int acc = 0;
        for (int e = 0; e < Ee; e++) {
            g_off[e] = acc;
            acc += ((g_cnt[e] + 127) >> 7) << 7;
        }
        g_off[Ee] = acc;
    }
}

__global__ void k_gather(const float* __restrict__ X)
{
    int t = blockIdx.x, tid = threadIdx.x;
    __shared__ int spos[TOPK];
    if (tid == 0) {
#pragma unroll
        for (int k = 0; k < TOPK; k++) {
            int e = g_tok_e[t * 2 + k];
            int p = g_off[e] + atomicAdd(&g_cur[e], 1);
            spos[k] = p;
            g_tok_pos[t * 2 + k] = p;
        }
    }
    __syncthreads();
    const float4* src = reinterpret_cast<const float4*>(X + (size_t)t * Dm);
#pragma unroll
    for (int k = 0; k < TOPK; k++) {
        float4* dst = reinterpret_cast<float4*>(g_XG + (size_t)spos[k] * Dm);
        dst[tid] = src[tid];
    }
}

__global__ void k_aux_final(float* __restrict__ out)
{
    int tid = threadIdx.x;
    float imp[Ee];
#pragma unroll
    for (int e = 0; e < Ee; e++) imp[e] = 0.f;
    for (int t = tid; t < Ntok; t += 256)
#pragma unroll
        for (int e = 0; e < Ee; e++) imp[e] += g_auxp[t * Ee + e];
    float ld[Ee];
#pragma unroll
    for (int e = 0; e < Ee; e++) ld[e] = 0.f;
    for (int i = tid; i < Ntok * TOPK; i += 256) ld[g_auxi[i]] += 1.f;

    __shared__ float red[256 * Ee];
    __shared__ float simp[Ee];
#pragma unroll
    for (int e = 0; e < Ee; e++) red[tid * Ee + e] = imp[e];
    __syncthreads();
    for (int st = 128; st > 0; st >>= 1) {
        if (tid < st)
#pragma unroll
            for (int e = 0; e < Ee; e++)
                red[tid * Ee + e] += red[(tid + st) * Ee + e];
        __syncthreads();
    }
    if (tid == 0)
#pragma unroll
        for (int e = 0; e < Ee; e++) simp[e] = red[e];
    __syncthreads();
#pragma unroll
    for (int e = 0; e < Ee; e++) red[tid * Ee + e] = ld[e];
    __syncthreads();
    for (int st = 128; st > 0; st >>= 1) {
        if (tid < st)
#pragma unroll
            for (int e = 0; e < Ee; e++)
                red[tid * Ee + e] += red[(tid + st) * Ee + e];
        __syncthreads();
    }
    if (tid == 0) {
        float aux = 0.f;
#pragma unroll
        for (int e = 0; e < Ee; e++)
            aux += (simp[e] / (float)Ntok) * (red[e] / (float)(Ntok * TOPK));
        out[0] = (float)Ee * aux;
    }
}

// ---------------- host orchestration ----------------
extern "C" void kernel_launch(void* const* d_in, const int* in_sizes, int n_in,
                              void* d_out, int out_size)
{
    (void)in_sizes; (void)n_in;
    const float* x     = (const float*)d_in[0];
    const float* enc   = (const float*)d_in[1];
    const float* sa_wq = (const float*)d_in[2];
    const float* sa_bq = (const float*)d_in[3];
    const float* sa_wk = (const float*)d_in[4];
    const float* sa_bk = (const float*)d_in[5];
    const float* sa_wv = (const float*)d_in[6];
    const float* sa_bv = (const float*)d_in[7];
    const float* sa_wo = (const float*)d_in[8];
    const float* sa_bo = (const float*)d_in[9];
    const float* ca_wq = (const float*)d_in[10];
    const float* ca_bq = (const float*)d_in[11];
    const float* ca_wk = (const float*)d_in[12];
    const float* ca_bk = (const float*)d_in[13];
    const float* ca_wv = (const float*)d_in[14];
    const float* ca_bv = (const float*)d_in[15];
    const float* ca_wo = (const float*)d_in[16];
    const float* ca_bo = (const float*)d_in[17];
    const float* n1_g  = (const float*)d_in[18];
    const float* n1_b  = (const float*)d_in[19];
    const float* n2_g  = (const float*)d_in[20];
    const float* n2_b  = (const float*)d_in[21];
    const float* n3_g  = (const float*)d_in[22];
    const float* n3_b  = (const float*)d_in[23];
    const float* r_w   = (const float*)d_in[24];
    const float* r_b   = (const float*)d_in[25];
    const float* e_w1  = (const float*)d_in[26];
    const float* e_b1  = (const float*)d_in[27];
    const float* e_w2  = (const float*)d_in[28];
    const float* e_b2  = (const float*)d_in[29];

    void *pQ, *pK, *pV, *pAT, *pPR, *pX1, *pX2, *pXG, *pHB, *pYG;
    cudaGetSymbolAddress(&pQ,  g_Q);
    cudaGetSymbolAddress(&pK,  g_K);
    cudaGetSymbolAddress(&pV,  g_V);
    cudaGetSymbolAddress(&pAT, g_AT);
    cudaGetSymbolAddress(&pPR, g_PR);
    cudaGetSymbolAddress(&pX1, g_X1);
    cudaGetSymbolAddress(&pX2, g_X2);
    cudaGetSymbolAddress(&pXG, g_XG);
    cudaGetSymbolAddress(&pHB, g_HB);
    cudaGetSymbolAddress(&pYG, g_YG);
    float* Q  = (float*)pQ;  float* K  = (float*)pK;  float* V  = (float*)pV;
    float* AT = (float*)pAT; float* PR = (float*)pPR;
    float* X1 = (float*)pX1; float* X2 = (float*)pX2;
    float* XG = (float*)pXG; float* HB = (float*)pHB; float* YG = (float*)pYG;
    float* out = (float*)d_out;

    static int smem_set = 0;
    if (!smem_set) {
        cudaFuncSetAttribute(k_flash, cudaFuncAttributeMaxDynamicSharedMemorySize, FLASH_SMEM);
        cudaFuncSetAttribute(k_gemm128, cudaFuncAttributeMaxDynamicSharedMemorySize, GEMM_SMEM);
        cudaFuncSetAttribute(k_gemm_batch3, cudaFuncAttributeMaxDynamicSharedMemorySize, GEMM_SMEM);
        cudaFuncSetAttribute(k_moe_gemm_mma, cudaFuncAttributeMaxDynamicSharedMemorySize, GEMM_SMEM);
        smem_set = 1;
    }

    dim3 gblk(128);
    dim3 blk(256);
    dim3 gProj(Ntok / 128, Dm / 128);
    dim3 gProj3(Ntok / 128, Dm / 128, 3);
    dim3 gFlash(Sseq / QT, Bbat * Hh);

    // ---- self attention ----
    {
        Ptr3 p;
        p.a[0] = x; p.a[1] = x; p.a[2] = x;
        p.b[0] = sa_wq; p.b[1] = sa_wk; p.b[2] = sa_wv;
        p.bias[0] = sa_bq; p.bias[1] = sa_bk; p.bias[2] = sa_bv;
        p.c[0] = Q; p.c[1] = K; p.c[2] = V;
        k_gemm_batch3<<<gProj3, gblk, GEMM_SMEM>>>(p);
    }
    k_flash<<<gFlash, blk, FLASH_SMEM>>>(Q, K, V, AT);
    k_gemm128<<<gProj, gblk, GEMM_SMEM>>>(AT, Dm, sa_wo, Dm, sa_bo, PR, Dm, Ntok, Dm, 0);
    k_ln_res<<<Ntok, blk>>>(x, PR, n1_g, n1_b, X1);

    // ---- cross attention ----
    {
        Ptr3 p;
        p.a[0] = X1; p.a[1] = enc; p.a[2] = enc;
        p.b[0] = ca_wq; p.b[1] = ca_wk; p.b[2] = ca_wv;
        p.bias[0] = ca_bq; p.bias[1] = ca_bk; p.bias[2] = ca_bv;
        p.c[0] = Q; p.c[1] = K; p.c[2] = V;
        k_gemm_batch3<<<gProj3, gblk, GEMM_SMEM>>>(p);
    }
    k_flash<<<gFlash, blk, FLASH_SMEM>>>(Q, K, V, AT);
    k_gemm128<<<gProj, gblk, GEMM_SMEM>>>(AT, Dm, ca_wo, Dm, ca_bo, PR, Dm, Ntok, Dm, 0);

    // ---- ln2 fused with dispatch router ----
    k_moe_init<<<1, 32>>>();
    k_ln_router<<<Ntok, blk>>>(X1, PR, n2_g, n2_b, X2, r_w, r_b);

    // ---- MoE ----
    k_offsets<<<1, 1>>>();
    k_gather<<<Ntok, blk>>>(X2);
    k_moe_gemm_mma<<<dim3(Ntok / 128, Ff / 128, Ee), gblk, GEMM_SMEM>>>(XG, e_w1, e_b1, HB, Dm, Ff, 1);
    k_moe_gemm_mma<<<dim3(Ntok / 128, Dm / 128, Ee), gblk, GEMM_SMEM>>>(HB, e_w2, e_b2, YG, Ff, Dm, 0);
    k_moe_out<<<Ntok, blk>>>(X2, n3_g, n3_b, out, r_w, r_b);

    // ---- aux scalar ----
    if (out_size > Ntok * Dm) {
        k_aux_final<<<1, blk>>>(out + (out_size - 1));
    }
}

// round 9
// speedup vs baseline: 1.3865x; 1.3865x over previous
#include <cuda_runtime.h>
#include <math.h>
#include <stdint.h>

// ---------------- problem constants ----------------
#define Dm      1024
#define Hh      16
#define DHd     64
#define Ff      4096
#define Ee      8
#define TOPK    2
#define Bbat    2
#define Sseq    2048
#define Ntok    4096
#define NKCAP   16384

// fp16 GEMM tiling: 128x128x64 tile, 128 threads (4 warps of 64x64)
// smem words (u32 = f16x2)
#define APW 36
#define BPW 136
#define H_ASZ (128 * APW)
#define H_BSZ (32 * BPW)
#define H_STG (H_ASZ + H_BSZ)
#define H_NSTAGE 3
#define H_SMEM (H_NSTAGE * H_STG * 4)

// flash tiling (register-staged, proven)
#define QT      128
#define KC      64
#define KSP     68
#define VSP     72
#define PSP     68
#define FLASH_SMEM ((KC*KSP + KC*VSP + QT*PSP) * 4)

// ---------------- device scratch ----------------
__device__ float g_Q [Ntok * Dm];
__device__ float g_K [Ntok * Dm];
__device__ float g_V [Ntok * Dm];
__device__ float g_PR[Ntok * Dm];
__device__ float g_X1[Ntok * Dm];
__device__ float g_X2[Ntok * Dm];
__device__ float g_YG[(size_t)NKCAP * Dm];

// fp16 packed (u32 = 2 halves along k)
__device__ unsigned g_xh  [Ntok * Dm / 2];
__device__ unsigned g_ench[Ntok * Dm / 2];
__device__ unsigned g_X1h [Ntok * Dm / 2];
__device__ unsigned g_ATh [Ntok * Dm / 2];
__device__ unsigned g_wh  [8][(Dm / 2) * Dm];         // 8 projection weights
__device__ unsigned g_e1h [(size_t)Ee * (Dm / 2) * Ff];
__device__ unsigned g_e2h [(size_t)Ee * (Ff / 2) * Dm];
__device__ unsigned g_XGh [(size_t)NKCAP * Dm / 2];
__device__ unsigned g_HBh [(size_t)NKCAP * Ff / 2];

__device__ int   g_tok_e[Ntok * TOPK];
__device__ float g_tok_g[Ntok * TOPK];
__device__ int   g_tok_pos[Ntok * TOPK];
__device__ int   g_cnt[Ee];
__device__ int   g_cur[Ee];
__device__ int   g_off[Ee + 1];
__device__ float g_auxp[Ntok * Ee];
__device__ int   g_auxi[Ntok * TOPK];

// ---------------- helpers ----------------
__device__ __forceinline__ unsigned packh(float lo, float hi) {
    unsigned r;
    asm("cvt.rn.f16x2.f32 %0, %1, %2;" : "=r"(r) : "f"(hi), "f"(lo));
    return r;
}

__device__ __forceinline__ void mma16(float* c, const unsigned* a, const unsigned* b) {
    asm volatile(
        "mma.sync.aligned.m16n8k16.row.col.f32.f16.f16.f32 "
        "{%0,%1,%2,%3},{%4,%5,%6,%7},{%8,%9},{%0,%1,%2,%3};\n"
        : "+f"(c[0]), "+f"(c[1]), "+f"(c[2]), "+f"(c[3])
        : "r"(a[0]), "r"(a[1]), "r"(a[2]), "r"(a[3]), "r"(b[0]), "r"(b[1]));
}

__device__ __forceinline__ void cp16(void* smem, const void* gmem, bool pred) {
    unsigned saddr = (unsigned)__cvta_generic_to_shared(smem);
    int sz = pred ? 16 : 0;
    asm volatile("cp.async.ca.shared.global [%0], [%1], 16, %2;\n"
                 :: "r"(saddr), "l"(gmem), "r"(sz));
}
__device__ __forceinline__ void cp_commit() {
    asm volatile("cp.async.commit_group;\n");
}
__device__ __forceinline__ void cp_wait1() {
    asm volatile("cp.async.wait_group 1;\n" ::: "memory");
}

// ---------------- fp16 conversions ----------------
// A-style: [M][K] f32 -> [M][K/2] words (pack adjacent k)
__global__ void k_cvtA(const float* __restrict__ src, unsigned* __restrict__ dst, int nquads)
{
    int i = blockIdx.x * blockDim.x + threadIdx.x;
    if (i >= nquads) return;
    float4 v = ((const float4*)src)[i];
    ((uint2*)dst)[i] = make_uint2(packh(v.x, v.y), packh(v.z, v.w));
}

// B-style: [K][N] f32 -> [K/2][N] words (word(kp,n) = pack(B[2kp][n], B[2kp+1][n]))
__global__ void k_cvtB(const float* __restrict__ src, unsigned* __restrict__ dst, int K, int N)
{
    int i = blockIdx.x * blockDim.x + threadIdx.x;
    int nq = N >> 2;
    int total = (K >> 1) * nq;
    if (i >= total) return;
    int kp = i / nq, n4 = i - kp * nq;
    float4 a = *(const float4*)(src + (size_t)(2 * kp) * N + n4 * 4);
    float4 b = *(const float4*)(src + (size_t)(2 * kp + 1) * N + n4 * 4);
    uint4 w;
    w.x = packh(a.x, b.x); w.y = packh(a.y, b.y);
    w.z = packh(a.z, b.z); w.w = packh(a.w, b.w);
    *(uint4*)(dst + (size_t)kp * N + n4 * 4) = w;
}

// ---------------- fp16 GEMM: 128x128x64 tile, 3-stage cp.async ----------------
__device__ __forceinline__ void h_stage(
    unsigned* As, unsigned* Bs,
    const unsigned* __restrict__ Ah, int ldaw,
    const unsigned* __restrict__ Bh, int ldbw,
    int bm, int bn, int kw0, int M, int tid)
{
#pragma unroll
    for (int i = 0; i < 8; i++) {
        int c = tid + i * 128;
        int r = c >> 3, cw = (c & 7) << 2;
        bool p = (bm + r) < M;
        const unsigned* src = Ah + (size_t)(p ? (bm + r) : 0) * ldaw + kw0 + cw;
        cp16(&As[r * APW + cw], src, p);
    }
#pragma unroll
    for (int i = 0; i < 8; i++) {
        int c = tid + i * 128;
        int r = c >> 5, cw = (c & 31) << 2;
        cp16(&Bs[r * BPW + cw], Bh + (size_t)(kw0 + r) * ldbw + bn + cw, true);
    }
}

__device__ __forceinline__ void h_gemm_tile(
    const unsigned* __restrict__ Ah, int ldaw,
    const unsigned* __restrict__ Bh, int ldbw,
    const float* __restrict__ bias,
    float* __restrict__ Cf, unsigned* __restrict__ Ch, int ldc,
    int M, int Kd, int bm, int bn, int relu)
{
    extern __shared__ unsigned smp[];

    const int tid  = threadIdx.x;
    const int lane = tid & 31;
    const int wid  = tid >> 5;
    const int wm = (wid >> 1) * 64;
    const int wn = (wid & 1) * 64;
    const int g  = lane >> 2;
    const int tg = lane & 3;

    float acc[4][8][4];
#pragma unroll
    for (int i = 0; i < 4; i++)
#pragma unroll
        for (int j = 0; j < 8; j++)
#pragma unroll
            for (int q = 0; q < 4; q++) acc[i][j][q] = 0.f;

    const int T = Kd / 64;   // 32 words of K per tile

    h_stage(smp, smp + H_ASZ, Ah, ldaw, Bh, ldbw, bm, bn, 0, M, tid);
    cp_commit();
    h_stage(smp + H_STG, smp + H_STG + H_ASZ, Ah, ldaw, Bh, ldbw, bm, bn, 32, M, tid);
    cp_commit();

    for (int t = 0; t < T; t++) {
        cp_wait1();
        __syncthreads();

        if (t + 2 < T) {
            unsigned* dst = smp + ((t + 2) % H_NSTAGE) * H_STG;
            h_stage(dst, dst + H_ASZ, Ah, ldaw, Bh, ldbw, bm, bn, (t + 2) * 32, M, tid);
        }
        cp_commit();

        const unsigned* As = smp + (t % H_NSTAGE) * H_STG;
        const unsigned* Bs = As + H_ASZ;

#pragma unroll
        for (int ks = 0; ks < 4; ks++) {   // 4 x k16 steps
            const int kp0 = ks * 8;
            unsigned af[4][4], bf[8][2];
#pragma unroll
            for (int mt = 0; mt < 4; mt++) {
                int mb = wm + mt * 16;
                af[mt][0] = As[(mb + g)     * APW + kp0 + tg];
                af[mt][1] = As[(mb + g + 8) * APW + kp0 + tg];
                af[mt][2] = As[(mb + g)     * APW + kp0 + tg + 4];
                af[mt][3] = As[(mb + g + 8) * APW + kp0 + tg + 4];
            }
#pragma unroll
            for (int nt = 0; nt < 8; nt++) {
                int nb = wn + nt * 8;
                bf[nt][0] = Bs[(kp0 + tg)     * BPW + nb + g];
                bf[nt][1] = Bs[(kp0 + tg + 4) * BPW + nb + g];
            }
#pragma unroll
            for (int mt = 0; mt < 4; mt++)
#pragma unroll
                for (int nt = 0; nt < 8; nt++)
                    mma16(acc[mt][nt], af[mt], bf[nt]);
        }
    }

#pragma unroll
    for (int mt = 0; mt < 4; mt++) {
#pragma unroll
        for (int nt = 0; nt < 8; nt++) {
            int row0 = bm + wm + mt * 16 + g;
            int col  = bn + wn + nt * 8 + tg * 2;
            float b0 = bias ? bias[col]     : 0.f;
            float b1 = bias ? bias[col + 1] : 0.f;
            float v0 = acc[mt][nt][0] + b0;
            float v1 = acc[mt][nt][1] + b1;
            float v2 = acc[mt][nt][2] + b0;
            float v3 = acc[mt][nt][3] + b1;
            if (relu) {
                v0 = fmaxf(v0, 0.f); v1 = fmaxf(v1, 0.f);
                v2 = fmaxf(v2, 0.f); v3 = fmaxf(v3, 0.f);
            }
            if (Ch) {
                int colw = col >> 1;
                int ldw = ldc >> 1;
                if (row0 < M)     Ch[(size_t)row0 * ldw + colw]       = packh(v0, v1);
                if (row0 + 8 < M) Ch[(size_t)(row0 + 8) * ldw + colw] = packh(v2, v3);
            } else {
                if (row0 < M)     *(float2*)(Cf + (size_t)row0 * ldc + col)       = make_float2(v0, v1);
                if (row0 + 8 < M) *(float2*)(Cf + (size_t)(row0 + 8) * ldc + col) = make_float2(v2, v3);
            }
        }
    }
}

__global__ void __launch_bounds__(128) k_gemm_h(
    const unsigned* __restrict__ Ah, int ldaw, const unsigned* __restrict__ Bh, int ldbw,
    const float* __restrict__ bias, float* __restrict__ Cf, unsigned* __restrict__ Ch,
    int ldc, int M, int Kd, int relu)
{
    h_gemm_tile(Ah, ldaw, Bh, ldbw, bias, Cf, Ch, ldc, M, Kd,
                blockIdx.x * 128, blockIdx.y * 128, relu);
}

__global__ void __launch_bounds__(128) k_moe_gemm_h(
    const unsigned* __restrict__ Abase, const unsigned* __restrict__ Wbase,
    const float* __restrict__ bbase, float* __restrict__ Cf, unsigned* __restrict__ Ch,
    int Kd, int Nn, int relu)
{
    int e = blockIdx.z;
    int cnt = g_cnt[e];
    int bm = blockIdx.x * 128;
    if (bm >= cnt) return;
    int off = g_off[e];
    int kw = Kd >> 1;
    h_gemm_tile(Abase + (size_t)off * kw, kw,
                Wbase + (size_t)e * kw * Nn, Nn,
                bbase + (size_t)e * Nn,
                Cf ? Cf + (size_t)off * Nn : (float*)0,
                Ch ? Ch + (size_t)off * (Nn >> 1) : (unsigned*)0,
                Nn, cnt, Kd, bm, blockIdx.y * 128, relu);
}

// ---------------- tf32 helpers for flash ----------------
__device__ __forceinline__ unsigned f2tf(float f) {
    unsigned r;
    asm("cvt.rna.tf32.f32 %0, %1;" : "=r"(r) : "f"(f));
    return r;
}
__device__ __forceinline__ void mma_tf32(float* c, const unsigned* a, const unsigned* b) {
    asm volatile(
        "mma.sync.aligned.m16n8k8.row.col.f32.tf32.tf32.f32 "
        "{%0,%1,%2,%3},{%4,%5,%6,%7},{%8,%9},{%0,%1,%2,%3};\n"
        : "+f"(c[0]), "+f"(c[1]), "+f"(c[2]), "+f"(c[3])
        : "r"(a[0]), "r"(a[1]), "r"(a[2]), "r"(a[3]), "r"(b[0]), "r"(b[1]));
}

// ---------------- flash attention (register-staged; epilogue -> packed fp16 AT) ----------------
__global__ void __launch_bounds__(256) k_flash(
    const float* __restrict__ Qg, const float* __restrict__ Kg,
    const float* __restrict__ Vg, unsigned* __restrict__ ATh)
{
    extern __shared__ float sm[];
    unsigned* Ks = (unsigned*)sm;
    unsigned* Vs = Ks + KC * KSP;
    unsigned* Ps = Vs + KC * VSP;

    const int bh = blockIdx.y;
    const int b = bh >> 4, h = bh & 15;
    const int q0 = blockIdx.x * QT;
    const int tid = threadIdx.x;
    const int lane = tid & 31;
    const int wid = tid >> 5;
    const int g = lane >> 2;
    const int tg = lane & 3;
    const int wrow = wid * 16;

    const float* Qp = Qg + (size_t)b * Sseq * Dm + h * DHd;
    const float* Kp = Kg + (size_t)b * Sseq * Dm + h * DHd;
    const float* Vp = Vg + (size_t)b * Sseq * Dm + h * DHd;

    unsigned qf[8][4];
#pragma unroll
    for (int kt = 0; kt < 8; kt++) {
        int k = kt * 8;
        qf[kt][0] = f2tf(Qp[(size_t)(q0 + wrow + g)     * Dm + k + tg]);
        qf[kt][1] = f2tf(Qp[(size_t)(q0 + wrow + g + 8) * Dm + k + tg]);
        qf[kt][2] = f2tf(Qp[(size_t)(q0 + wrow + g)     * Dm + k + tg + 4]);
        qf[kt][3] = f2tf(Qp[(size_t)(q0 + wrow + g + 8) * Dm + k + tg + 4]);
    }

    float oacc[8][4];
#pragma unroll
    for (int i = 0; i < 8; i++)
#pragma unroll
        for (int j = 0; j < 4; j++) oacc[i][j] = 0.f;
    float m0 = -1e30f, m1 = -1e30f, l0 = 0.f, l1 = 0.f;

    for (int c = 0; c < Sseq / KC; c++) {
        int kc0 = c * KC;
#pragma unroll
        for (int i = 0; i < 4; i++) {
            int idx = tid + i * 256;
            int r = idx >> 4, cc = (idx & 15) << 2;
            float4 kv = *(const float4*)(Kp + (size_t)(kc0 + r) * Dm + cc);
            unsigned* p = &Ks[r * KSP + cc];
            p[0] = f2tf(kv.x); p[1] = f2tf(kv.y); p[2] = f2tf(kv.z); p[3] = f2tf(kv.w);
            float4 vv = *(const float4*)(Vp + (size_t)(kc0 + r) * Dm + cc);
            unsigned* q = &Vs[r * VSP + cc];
            q[0] = f2tf(vv.x); q[1] = f2tf(vv.y); q[2] = f2tf(vv.z); q[3] = f2tf(vv.w);
        }
        __syncthreads();

        float sacc[8][4];
#pragma unroll
        for (int i = 0; i < 8; i++)
#pragma unroll
            for (int j = 0; j < 4; j++) sacc[i][j] = 0.f;
#pragma unroll
        for (int kt = 0; kt < 8; kt++) {
            int k = kt * 8;
            unsigned bf[8][2];
#pragma unroll
            for (int nt = 0; nt < 8; nt++) {
                bf[nt][0] = Ks[(nt * 8 + g) * KSP + k + tg];
                bf[nt][1] = Ks[(nt * 8 + g) * KSP + k + tg + 4];
            }
#pragma unroll
            for (int nt = 0; nt < 8; nt++)
                mma_tf32(sacc[nt], qf[kt], bf[nt]);
        }

        float mx0 = -1e30f, mx1 = -1e30f;
#pragma unroll
        for (int nt = 0; nt < 8; nt++) {
            sacc[nt][0] *= 0.125f; sacc[nt][1] *= 0.125f;
            sacc[nt][2] *= 0.125f; sacc[nt][3] *= 0.125f;
            mx0 = fmaxf(mx0, fmaxf(sacc[nt][0], sacc[nt][1]));
            mx1 = fmaxf(mx1, fmaxf(sacc[nt][2], sacc[nt][3]));
        }
        mx0 = fmaxf(mx0, __shfl_xor_sync(0xffffffff, mx0, 1));
        mx0 = fmaxf(mx0, __shfl_xor_sync(0xffffffff, mx0, 2));
        mx1 = fmaxf(mx1, __shfl_xor_sync(0xffffffff, mx1, 1));
        mx1 = fmaxf(mx1, __shfl_xor_sync(0xffffffff, mx1, 2));
        float nm0 = fmaxf(m0, mx0), nm1 = fmaxf(m1, mx1);
        float sc0 = __expf(m0 - nm0), sc1 = __expf(m1 - nm1);
        float ps0 = 0.f, ps1 = 0.f;
#pragma unroll
        for (int nt = 0; nt < 8; nt++) {
            float p00 = __expf(sacc[nt][0] - nm0);
            float p01 = __expf(sacc[nt][1] - nm0);
            float p10 = __expf(sacc[nt][2] - nm1);
            float p11 = __expf(sacc[nt][3] - nm1);
            ps0 += p00 + p01; ps1 += p10 + p11;
            int col = nt * 8 + tg * 2;
            *(uint2*)&Ps[(wrow + g)     * PSP + col] = make_uint2(f2tf(p00), f2tf(p01));
            *(uint2*)&Ps[(wrow + g + 8) * PSP + col] = make_uint2(f2tf(p10), f2tf(p11));
        }
        ps0 += __shfl_xor_sync(0xffffffff, ps0, 1);
        ps0 += __shfl_xor_sync(0xffffffff, ps0, 2);
        ps1 += __shfl_xor_sync(0xffffffff, ps1, 1);
        ps1 += __shfl_xor_sync(0xffffffff, ps1, 2);
        l0 = l0 * sc0 + ps0; l1 = l1 * sc1 + ps1;
        m0 = nm0; m1 = nm1;
#pragma unroll
        for (int nt = 0; nt < 8; nt++) {
            oacc[nt][0] *= sc0; oacc[nt][1] *= sc0;
            oacc[nt][2] *= sc1; oacc[nt][3] *= sc1;
        }
        __syncwarp();

#pragma unroll
        for (int kt = 0; kt < 8; kt++) {
            int k = kt * 8;
            unsigned af[4];
            af[0] = Ps[(wrow + g)     * PSP + k + tg];
            af[1] = Ps[(wrow + g + 8) * PSP + k + tg];
            af[2] = Ps[(wrow + g)     * PSP + k + tg + 4];
            af[3] = Ps[(wrow + g + 8) * PSP + k + tg + 4];
            unsigned bf[8][2];
#pragma unroll
            for (int nt = 0; nt < 8; nt++) {
                bf[nt][0] = Vs[(k + tg)     * VSP + nt * 8 + g];
                bf[nt][1] = Vs[(k + tg + 4) * VSP + nt * 8 + g];
            }
#pragma unroll
            for (int nt = 0; nt < 8; nt++)
                mma_tf32(oacc[nt], af, bf[nt]);
        }
        __syncthreads();
    }

    float inv0 = 1.f / l0, inv1 = 1.f / l1;
    const size_t r0 = (size_t)(b * Sseq + q0 + wrow + g) * (Dm / 2);
    const size_t r1 = (size_t)(b * Sseq + q0 + wrow + g + 8) * (Dm / 2);
#pragma unroll
    for (int nt = 0; nt < 8; nt++) {
        int colw = h * 32 + nt * 4 + tg;
        ATh[r0 + colw] = packh(oacc[nt][0] * inv0, oacc[nt][1] * inv0);
        ATh[r1 + colw] = packh(oacc[nt][2] * inv1, oacc[nt][3] * inv1);
    }
}

// ---------------- layernorm(residual) with optional fp16 output ----------------
__global__ void k_ln_res(const float* __restrict__ X, const float* __restrict__ R,
                         const float* __restrict__ gw, const float* __restrict__ bw,
                         float* __restrict__ O, unsigned* __restrict__ Oh)
{
    int t = blockIdx.x, tid = threadIdx.x;
    const float2* xp = (const float2*)(X + (size_t)t * Dm);
    const float2* rp = (const float2*)(R + (size_t)t * Dm);
    float2 v[2]; float s = 0.f;
#pragma unroll
    for (int i = 0; i < 2; i++) {
        int d2 = tid + i * 256;
        float2 a = xp[d2], b = rp[d2];
        v[i].x = a.x + b.x; v[i].y = a.y + b.y;
        s += v[i].x + v[i].y;
    }
    __shared__ float red[256];
    red[tid] = s; __syncthreads();
    for (int st = 128; st > 0; st >>= 1) {
        if (tid < st) red[tid] += red[tid + st];
        __syncthreads();
    }
    float mean = red[0] * (1.f / Dm);
    __syncthreads();
    float s2 = 0.f;
#pragma unroll
    for (int i = 0; i < 2; i++) {
        float dx = v[i].x - mean, dy = v[i].y - mean;
        s2 += dx * dx + dy * dy;
    }
    red[tid] = s2; __syncthreads();
    for (int st = 128; st > 0; st >>= 1) {
        if (tid < st) red[tid] += red[tid + st];
        __syncthreads();
    }
    float rstd = rsqrtf(red[0] * (1.f / Dm) + 1e-5f);
    float2* op = (float2*)(O + (size_t)t * Dm);
    const float2* gp = (const float2*)gw;
    const float2* bp = (const float2*)bw;
#pragma unroll
    for (int i = 0; i < 2; i++) {
        int d2 = tid + i * 256;
        float2 gg = gp[d2], bb = bp[d2];
        float ox = (v[i].x - mean) * rstd * gg.x + bb.x;
        float oy = (v[i].y - mean) * rstd * gg.y + bb.y;
        op[d2] = make_float2(ox, oy);
        if (Oh) Oh[(size_t)t * (Dm / 2) + d2] = packh(ox, oy);
    }
}

// ---------------- fused MoE combine + layernorm ----------------
__global__ void k_moe_out(const float* __restrict__ X2,
                          const float* __restrict__ gw, const float* __restrict__ bw,
                          float* __restrict__ O)
{
    int t = blockIdx.x, tid = threadIdx.x;
    int p0 = g_tok_pos[t * 2], p1 = g_tok_pos[t * 2 + 1];
    float w0 = g_tok_g[t * 2], w1 = g_tok_g[t * 2 + 1];
    const float* xp = X2 + (size_t)t * Dm;
    const float* y0 = g_YG + (size_t)p0 * Dm;
    const float* y1 = g_YG + (size_t)p1 * Dm;
    float v[4]; float s = 0.f;
#pragma unroll
    for (int i = 0; i < 4; i++) {
        int d = tid + i * 256;
        v[i] = xp[d] + w0 * y0[d] + w1 * y1[d];
        s += v[i];
    }
    __shared__ float red[256];
    red[tid] = s; __syncthreads();
    for (int st = 128; st > 0; st >>= 1) {
        if (tid < st) red[tid] += red[tid + st];
        __syncthreads();
    }
    float mean = red[0] * (1.f / Dm);
    __syncthreads();
    float s2 = 0.f;
#pragma unroll
    for (int i = 0; i < 4; i++) { float dd = v[i] - mean; s2 += dd * dd; }
    red[tid] = s2; __syncthreads();
    for (int st = 128; st > 0; st >>= 1) {
        if (tid < st) red[tid] += red[tid + st];
        __syncthreads();
    }
    float rstd = rsqrtf(red[0] * (1.f / Dm) + 1e-5f);
    float* op = O + (size_t)t * Dm;
#pragma unroll
    for (int i = 0; i < 4; i++) {
        int d = tid + i * 256;
        op[d] = (v[i] - mean) * rstd * gw[d] + bw[d];
    }
}

// ---------------- MoE routing / dispatch ----------------
__global__ void k_moe_init()
{
    int tid = threadIdx.x;
    if (tid < Ee) { g_cnt[tid] = 0; g_cur[tid] = 0; }
}

__global__ void k_router(const float* __restrict__ X,
                         const float* __restrict__ rw,
                         const float* __restrict__ rb,
                         int mode)
{
    int t = blockIdx.x, tid = threadIdx.x;
    const float* xp = X + (size_t)t * Dm;
    float loc[Ee];
#pragma unroll
    for (int e = 0; e < Ee; e++) loc[e] = 0.f;
    for (int d = tid; d < Dm; d += 256) {
        float xv = xp[d];
#pragma unroll
        for (int e = 0; e < Ee; e++) loc[e] += xv * rw[d * Ee + e];
    }
    __shared__ float red[256 * Ee];
#pragma unroll
    for (int e = 0; e < Ee; e++) red[tid * Ee + e] = loc[e];
    __syncthreads();
    for (int st = 128; st > 0; st >>= 1) {
        if (tid < st)
#pragma unroll
            for (int e = 0; e < Ee; e++)
                red[tid * Ee + e] += red[(tid + st) * Ee + e];
        __syncthreads();
    }
    if (tid == 0) {
        float lg[Ee], mx = -1e30f;
#pragma unroll
        for (int e = 0; e < Ee; e++) { lg[e] = red[e] + rb[e]; mx = fmaxf(mx, lg[e]); }
        float sm = 0.f;
#pragma unroll
        for (int e = 0; e < Ee; e++) { lg[e] = expf(lg[e] - mx); sm += lg[e]; }
        float inv = 1.f / sm;
#pragma unroll
        for (int e = 0; e < Ee; e++) lg[e] *= inv;
        int e0 = 0;
#pragma unroll
        for (int e = 1; e < Ee; e++) if (lg[e] > lg[e0]) e0 = e;
        int e1 = -1;
#pragma unroll
        for (int e = 0; e < Ee; e++)
            if (e != e0 && (e1 < 0 || lg[e] > lg[e1])) e1 = e;
        if (mode == 0) {
            float g0 = lg[e0], g1 = lg[e1], gs = g0 + g1;
            g_tok_e[t * 2] = e0;  g_tok_e[t * 2 + 1] = e1;
            g_tok_g[t * 2] = g0 / gs; g_tok_g[t * 2 + 1] = g1 / gs;
            atomicAdd(&g_cnt[e0], 1); atomicAdd(&g_cnt[e1], 1);
        } else {
#pragma unroll
            for (int e = 0; e < Ee; e++) g_auxp[t * Ee + e] = lg[e];
            g_auxi[t * 2] = e0; g_auxi[t * 2 + 1] = e1;
        }
    }
}

__global__ void k_offsets()
{
    if (threadIdx.x == 0) {
        int acc = 0;
        for (int e = 0; e < Ee; e++) {
            g_off[e] = acc;
            acc += ((g_cnt[e] + 127) >> 7) << 7;
        }
        g_off[Ee] = acc;
    }
}

__global__ void k_gather(const float* __restrict__ X)
{
    int t = blockIdx.x, tid = threadIdx.x;
    __shared__ int spos[TOPK];
    if (tid == 0) {
#pragma unroll
        for (int k = 0; k < TOPK; k++) {
            int e = g_tok_e[t * 2 + k];
            int p = g_off[e] + atomicAdd(&g_cur[e], 1);
            spos[k] = p;
            g_tok_pos[t * 2 + k] = p;
        }
    }
    __syncthreads();
    float4 v = reinterpret_cast<const float4*>(X + (size_t)t * Dm)[tid];
    uint2 w = make_uint2(packh(v.x, v.y), packh(v.z, v.w));
#pragma unroll
    for (int k = 0; k < TOPK; k++)
        reinterpret_cast<uint2*>(g_XGh + (size_t)spos[k] * (Dm / 2))[tid] = w;
}

__global__ void k_aux_final(float* __restrict__ out)
{
    int tid = threadIdx.x;
    float imp[Ee];
#pragma unroll
    for (int e = 0; e < Ee; e++) imp[e] = 0.f;
    for (int t = tid; t < Ntok; t += 256)
#pragma unroll
        for (int e = 0; e < Ee; e++) imp[e] += g_auxp[t * Ee + e];
    float ld[Ee];
#pragma unroll
    for (int e = 0; e < Ee; e++) ld[e] = 0.f;
    for (int i = tid; i < Ntok * TOPK; i += 256) ld[g_auxi[i]] += 1.f;

    __shared__ float red[256 * Ee];
    __shared__ float simp[Ee];
#pragma unroll
    for (int e = 0; e < Ee; e++) red[tid * Ee + e] = imp[e];
    __syncthreads();
    for (int st = 128; st > 0; st >>= 1) {
        if (tid < st)
#pragma unroll
            for (int e = 0; e < Ee; e++)
                red[tid * Ee + e] += red[(tid + st) * Ee + e];
        __syncthreads();
    }
    if (tid == 0)
#pragma unroll
        for (int e = 0; e < Ee; e++) simp[e] = red[e];
    __syncthreads();
#pragma unroll
    for (int e = 0; e < Ee; e++) red[tid * Ee + e] = ld[e];
    __syncthreads();
    for (int st = 128; st > 0; st >>= 1) {
        if (tid < st)
#pragma unroll
            for (int e = 0; e < Ee; e++)
                red[tid * Ee + e] += red[(tid + st) * Ee + e];
        __syncthreads();
    }
    if (tid == 0) {
        float aux = 0.f;
#pragma unroll
        for (int e = 0; e < Ee; e++)
            aux += (simp[e] / (float)Ntok) * (red[e] / (float)(Ntok * TOPK));
        out[0] = (float)Ee * aux;
    }
}

// ---------------- host orchestration ----------------
extern "C" void kernel_launch(void* const* d_in, const int* in_sizes, int n_in,
                              void* d_out, int out_size)
{
    (void)in_sizes; (void)n_in;
    const float* x     = (const float*)d_in[0];
    const float* enc   = (const float*)d_in[1];
    const float* sa_wq = (const float*)d_in[2];
    const float* sa_bq = (const float*)d_in[3];
    const float* sa_wk = (const float*)d_in[4];
    const float* sa_bk = (const float*)d_in[5];
    const float* sa_wv = (const float*)d_in[6];
    const float* sa_bv = (const float*)d_in[7];
    const float* sa_wo = (const float*)d_in[8];
    const float* sa_bo = (const float*)d_in[9];
    const float* ca_wq = (const float*)d_in[10];
    const float* ca_bq = (const float*)d_in[11];
    const float* ca_wk = (const float*)d_in[12];
    const float* ca_bk = (const float*)d_in[13];
    const float* ca_wv = (const float*)d_in[14];
    const float* ca_bv = (const float*)d_in[15];
    const float* ca_wo = (const float*)d_in[16];
    const float* ca_bo = (const float*)d_in[17];
    const float* n1_g  = (const float*)d_in[18];
    const float* n1_b  = (const float*)d_in[19];
    const float* n2_g  = (const float*)d_in[20];
    const float* n2_b  = (const float*)d_in[21];
    const float* n3_g  = (const float*)d_in[22];
    const float* n3_b  = (const float*)d_in[23];
    const float* r_w   = (const float*)d_in[24];
    const float* r_b   = (const float*)d_in[25];
    const float* e_w1  = (const float*)d_in[26];
    const float* e_b1  = (const float*)d_in[27];
    const float* e_w2  = (const float*)d_in[28];
    const float* e_b2  = (const float*)d_in[29];

    void *pQ, *pK, *pV, *pPR, *pX1, *pX2, *pYG;
    void *pxh, *pench, *pX1h, *pATh, *pwh, *pe1h, *pe2h, *pXGh, *pHBh;
    cudaGetSymbolAddress(&pQ,  g_Q);
    cudaGetSymbolAddress(&pK,  g_K);
    cudaGetSymbolAddress(&pV,  g_V);
    cudaGetSymbolAddress(&pPR, g_PR);
    cudaGetSymbolAddress(&pX1, g_X1);
    cudaGetSymbolAddress(&pX2, g_X2);
    cudaGetSymbolAddress(&pYG, g_YG);
    cudaGetSymbolAddress(&pxh,  g_xh);
    cudaGetSymbolAddress(&pench, g_ench);
    cudaGetSymbolAddress(&pX1h, g_X1h);
    cudaGetSymbolAddress(&pATh, g_ATh);
    cudaGetSymbolAddress(&pwh,  g_wh);
    cudaGetSymbolAddress(&pe1h, g_e1h);
    cudaGetSymbolAddress(&pe2h, g_e2h);
    cudaGetSymbolAddress(&pXGh, g_XGh);
    cudaGetSymbolAddress(&pHBh, g_HBh);
    float* Q  = (float*)pQ;  float* K = (float*)pK;  float* V = (float*)pV;
    float* PR = (float*)pPR; float* X1 = (float*)pX1; float* X2 = (float*)pX2;
    float* YG = (float*)pYG;
    unsigned* xh   = (unsigned*)pxh;
    unsigned* ench = (unsigned*)pench;
    unsigned* X1h  = (unsigned*)pX1h;
    unsigned* ATh  = (unsigned*)pATh;
    unsigned* wh   = (unsigned*)pwh;      // 8 matrices of 512*1024 words
    unsigned* e1h  = (unsigned*)pe1h;
    unsigned* e2h  = (unsigned*)pe2h;
    unsigned* XGh  = (unsigned*)pXGh;
    unsigned* HBh  = (unsigned*)pHBh;
    float* out = (float*)d_out;

    static int smem_set = 0;
    if (!smem_set) {
        cudaFuncSetAttribute(k_flash, cudaFuncAttributeMaxDynamicSharedMemorySize, FLASH_SMEM);
        cudaFuncSetAttribute(k_gemm_h, cudaFuncAttributeMaxDynamicSharedMemorySize, H_SMEM);
        cudaFuncSetAttribute(k_moe_gemm_h, cudaFuncAttributeMaxDynamicSharedMemorySize, H_SMEM);
        smem_set = 1;
    }

    dim3 gblk(128);
    dim3 blk(256);
    dim3 gProj(Ntok / 128, Dm / 128);
    dim3 gFlash(Sseq / QT, Bbat * Hh);
    const int WSTRIDE = (Dm / 2) * Dm;     // words per projection weight

    // ---- fp16 conversions (weights + primary activations) ----
    {
        int nq = Ntok * Dm / 4;
        k_cvtA<<<(nq + 255) / 256, 256>>>(x, xh, nq);
        k_cvtA<<<(nq + 255) / 256, 256>>>(enc, ench, nq);
        int bw = ((Dm / 2) * (Dm / 4) + 255) / 256;
        k_cvtB<<<bw, 256>>>(sa_wq, wh + 0 * WSTRIDE, Dm, Dm);
        k_cvtB<<<bw, 256>>>(sa_wk, wh + 1 * WSTRIDE, Dm, Dm);
        k_cvtB<<<bw, 256>>>(sa_wv, wh + 2 * WSTRIDE, Dm, Dm);
        k_cvtB<<<bw, 256>>>(sa_wo, wh + 3 * WSTRIDE, Dm, Dm);
        k_cvtB<<<bw, 256>>>(ca_wq, wh + 4 * WSTRIDE, Dm, Dm);
        k_cvtB<<<bw, 256>>>(ca_wk, wh + 5 * WSTRIDE, Dm, Dm);
        k_cvtB<<<bw, 256>>>(ca_wv, wh + 6 * WSTRIDE, Dm, Dm);
        k_cvtB<<<bw, 256>>>(ca_wo, wh + 7 * WSTRIDE, Dm, Dm);
        int b1 = ((Ee * Dm / 2) * (Ff / 4) + 255) / 256;
        k_cvtB<<<b1, 256>>>(e_w1, e1h, Ee * Dm, Ff);
        int b2 = ((Ee * Ff / 2) * (Dm / 4) + 255) / 256;
        k_cvtB<<<b2, 256>>>(e_w2, e2h, Ee * Ff, Dm);
    }

    // ---- self attention ----
    k_gemm_h<<<gProj, gblk, H_SMEM>>>(xh, Dm/2, wh + 0*WSTRIDE, Dm, sa_bq, Q, (unsigned*)0, Dm, Ntok, Dm, 0);
    k_gemm_h<<<gProj, gblk, H_SMEM>>>(xh, Dm/2, wh + 1*WSTRIDE, Dm, sa_bk, K, (unsigned*)0, Dm, Ntok, Dm, 0);
    k_gemm_h<<<gProj, gblk, H_SMEM>>>(xh, Dm/2, wh + 2*WSTRIDE, Dm, sa_bv, V, (unsigned*)0, Dm, Ntok, Dm, 0);
    k_flash<<<gFlash, blk, FLASH_SMEM>>>(Q, K, V, ATh);
    k_gemm_h<<<gProj, gblk, H_SMEM>>>(ATh, Dm/2, wh + 3*WSTRIDE, Dm, sa_bo, PR, (unsigned*)0, Dm, Ntok, Dm, 0);
    k_ln_res<<<Ntok, blk>>>(x, PR, n1_g, n1_b, X1, X1h);

    // ---- cross attention ----
    k_gemm_h<<<gProj, gblk, H_SMEM>>>(X1h,  Dm/2, wh + 4*WSTRIDE, Dm, ca_bq, Q, (unsigned*)0, Dm, Ntok, Dm, 0);
    k_gemm_h<<<gProj, gblk, H_SMEM>>>(ench, Dm/2, wh + 5*WSTRIDE, Dm, ca_bk, K, (unsigned*)0, Dm, Ntok, Dm, 0);
    k_gemm_h<<<gProj, gblk, H_SMEM>>>(ench, Dm/2, wh + 6*WSTRIDE, Dm, ca_bv, V, (unsigned*)0, Dm, Ntok, Dm, 0);
    k_flash<<<gFlash, blk, FLASH_SMEM>>>(Q, K, V, ATh);
    k_gemm_h<<<gProj, gblk, H_SMEM>>>(ATh, Dm/2, wh + 7*WSTRIDE, Dm, ca_bo, PR, (unsigned*)0, Dm, Ntok, Dm, 0);
    k_ln_res<<<Ntok, blk>>>(X1, PR, n2_g, n2_b, X2, (unsigned*)0);

    // ---- MoE (sparse top-2 dispatch) ----
    k_moe_init<<<1, blk>>>();
    k_router<<<Ntok, blk>>>(X2, r_w, r_b, 0);
    k_offsets<<<1, 1>>>();
    k_gather<<<Ntok, blk>>>(X2);
    k_moe_gemm_h<<<dim3(Ntok / 128, Ff / 128, Ee), gblk, H_SMEM>>>(XGh, e1h, e_b1, (float*)0, HBh, Dm, Ff, 1);
    k_moe_gemm_h<<<dim3(Ntok / 128, Dm / 128, Ee), gblk, H_SMEM>>>(HBh, e2h, e_b2, YG, (unsigned*)0, Ff, Dm, 0);
    k_moe_out<<<Ntok, blk>>>(X2, n3_g, n3_b, out);

    // ---- aux loss (router recompute on OUTPUT, per reference) ----
    if (out_size > Ntok * Dm) {
        k_router<<<Ntok, blk>>>(out, r_w, r_b, 1);
        k_aux_final<<<1, blk>>>(out + (out_size - 1));
    }
}

// round 11
// speedup vs baseline: 1.6270x; 1.1734x over previous
#include <cuda_runtime.h>
#include <math.h>
#include <stdint.h>

// ---------------- problem constants ----------------
#define Dm      1024
#define Hh      16
#define DHd     64
#define Ff      4096
#define Ee      8
#define TOPK    2
#define Bbat    2
#define Sseq    2048
#define Ntok    4096
#define NKCAP   16384

// fp16 GEMM tiling: 128x128x64 tile, 128 threads (4 warps of 64x64)
#define APW 36
#define BPW 136
#define H_ASZ (128 * APW)
#define H_BSZ (32 * BPW)
#define H_STG (H_ASZ + H_BSZ)
#define H_NSTAGE 3
#define H_SMEM (H_NSTAGE * H_STG * 4)

// fp16 flash tiling (words = f16x2 along k)
#define QT    128
#define KC    64
#define KSW   36          // Ks row stride in words ([key][dh words])
#define VSW   72          // Vs row stride in words ([kc word][dh])
#define PSW   36          // Ps row stride in words ([q][kc words])
#define FLASH_SMEM ((KC*KSW + (KC/2)*VSW + QT*PSW) * 4)

// ---------------- device scratch ----------------
__device__ float g_V [Ntok * Dm];
__device__ float g_PR[Ntok * Dm];
__device__ float g_X1[Ntok * Dm];
__device__ float g_X2[Ntok * Dm];
__device__ float g_YG[(size_t)NKCAP * Dm];

__device__ unsigned g_Qh  [Ntok * Dm / 2];
__device__ unsigned g_Kh  [Ntok * Dm / 2];
__device__ unsigned g_xh  [Ntok * Dm / 2];
__device__ unsigned g_ench[Ntok * Dm / 2];
__device__ unsigned g_X1h [Ntok * Dm / 2];
__device__ unsigned g_ATh [Ntok * Dm / 2];
__device__ unsigned g_wh  [8][(Dm / 2) * Dm];
__device__ unsigned g_e1h [(size_t)Ee * (Dm / 2) * Ff];
__device__ unsigned g_e2h [(size_t)Ee * (Ff / 2) * Dm];
__device__ unsigned g_XGh [(size_t)NKCAP * Dm / 2];
__device__ unsigned g_HBh [(size_t)NKCAP * Ff / 2];

__device__ int   g_tok_e[Ntok * TOPK];
__device__ float g_tok_g[Ntok * TOPK];
__device__ int   g_tok_pos[Ntok * TOPK];
__device__ int   g_cnt[Ee];
__device__ int   g_cur[Ee];
__device__ int   g_off[Ee + 1];
__device__ float g_auxp[Ntok * Ee];
__device__ int   g_auxi[Ntok * TOPK];

// ---------------- helpers ----------------
__device__ __forceinline__ unsigned packh(float lo, float hi) {
    unsigned r;
    asm("cvt.rn.f16x2.f32 %0, %1, %2;" : "=r"(r) : "f"(hi), "f"(lo));
    return r;
}

__device__ __forceinline__ void mma16(float* c, const unsigned* a, const unsigned* b) {
    asm volatile(
        "mma.sync.aligned.m16n8k16.row.col.f32.f16.f16.f32 "
        "{%0,%1,%2,%3},{%4,%5,%6,%7},{%8,%9},{%0,%1,%2,%3};\n"
        : "+f"(c[0]), "+f"(c[1]), "+f"(c[2]), "+f"(c[3])
        : "r"(a[0]), "r"(a[1]), "r"(a[2]), "r"(a[3]), "r"(b[0]), "r"(b[1]));
}

__device__ __forceinline__ void cp16(void* smem, const void* gmem, bool pred) {
    unsigned saddr = (unsigned)__cvta_generic_to_shared(smem);
    int sz = pred ? 16 : 0;
    asm volatile("cp.async.ca.shared.global [%0], [%1], 16, %2;\n"
                 :: "r"(saddr), "l"(gmem), "r"(sz));
}
__device__ __forceinline__ void cp_commit() {
    asm volatile("cp.async.commit_group;\n");
}
__device__ __forceinline__ void cp_wait1() {
    asm volatile("cp.async.wait_group 1;\n" ::: "memory");
}

// ---------------- fp16 conversions ----------------
__global__ void k_cvtA(const float* __restrict__ src, unsigned* __restrict__ dst, int nquads)
{
    int i = blockIdx.x * blockDim.x + threadIdx.x;
    if (i >= nquads) return;
    float4 v = ((const float4*)src)[i];
    ((uint2*)dst)[i] = make_uint2(packh(v.x, v.y), packh(v.z, v.w));
}

__global__ void k_cvtB(const float* __restrict__ src, unsigned* __restrict__ dst, int K, int N)
{
    int i = blockIdx.x * blockDim.x + threadIdx.x;
    int nq = N >> 2;
    int total = (K >> 1) * nq;
    if (i >= total) return;
    int kp = i / nq, n4 = i - kp * nq;
    float4 a = *(const float4*)(src + (size_t)(2 * kp) * N + n4 * 4);
    float4 b = *(const float4*)(src + (size_t)(2 * kp + 1) * N + n4 * 4);
    uint4 w;
    w.x = packh(a.x, b.x); w.y = packh(a.y, b.y);
    w.z = packh(a.z, b.z); w.w = packh(a.w, b.w);
    *(uint4*)(dst + (size_t)kp * N + n4 * 4) = w;
}

// ---------------- fp16 GEMM: 128x128x64 tile, 3-stage cp.async ----------------
__device__ __forceinline__ void h_stage(
    unsigned* As, unsigned* Bs,
    const unsigned* __restrict__ Ah, int ldaw,
    const unsigned* __restrict__ Bh, int ldbw,
    int bm, int bn, int kw0, int M, int tid)
{
#pragma unroll
    for (int i = 0; i < 8; i++) {
        int c = tid + i * 128;
        int r = c >> 3, cw = (c & 7) << 2;
        bool p = (bm + r) < M;
        const unsigned* src = Ah + (size_t)(p ? (bm + r) : 0) * ldaw + kw0 + cw;
        cp16(&As[r * APW + cw], src, p);
    }
#pragma unroll
    for (int i = 0; i < 8; i++) {
        int c = tid + i * 128;
        int r = c >> 5, cw = (c & 31) << 2;
        cp16(&Bs[r * BPW + cw], Bh + (size_t)(kw0 + r) * ldbw + bn + cw, true);
    }
}

__device__ __forceinline__ void h_gemm_tile(
    const unsigned* __restrict__ Ah, int ldaw,
    const unsigned* __restrict__ Bh, int ldbw,
    const float* __restrict__ bias,
    float* __restrict__ Cf, unsigned* __restrict__ Ch, int ldc,
    int M, int Kd, int bm, int bn, int relu)
{
    extern __shared__ unsigned smp[];

    const int tid  = threadIdx.x;
    const int lane = tid & 31;
    const int wid  = tid >> 5;
    const int wm = (wid >> 1) * 64;
    const int wn = (wid & 1) * 64;
    const int g  = lane >> 2;
    const int tg = lane & 3;

    float acc[4][8][4];
#pragma unroll
    for (int i = 0; i < 4; i++)
#pragma unroll
        for (int j = 0; j < 8; j++)
#pragma unroll
            for (int q = 0; q < 4; q++) acc[i][j][q] = 0.f;

    const int T = Kd / 64;

    h_stage(smp, smp + H_ASZ, Ah, ldaw, Bh, ldbw, bm, bn, 0, M, tid);
    cp_commit();
    h_stage(smp + H_STG, smp + H_STG + H_ASZ, Ah, ldaw, Bh, ldbw, bm, bn, 32, M, tid);
    cp_commit();

    for (int t = 0; t < T; t++) {
        cp_wait1();
        __syncthreads();

        if (t + 2 < T) {
            unsigned* dst = smp + ((t + 2) % H_NSTAGE) * H_STG;
            h_stage(dst, dst + H_ASZ, Ah, ldaw, Bh, ldbw, bm, bn, (t + 2) * 32, M, tid);
        }
        cp_commit();

        const unsigned* As = smp + (t % H_NSTAGE) * H_STG;
        const unsigned* Bs = As + H_ASZ;

#pragma unroll
        for (int ks = 0; ks < 4; ks++) {
            const int kp0 = ks * 8;
            unsigned af[4][4], bf[8][2];
#pragma unroll
            for (int mt = 0; mt < 4; mt++) {
                int mb = wm + mt * 16;
                af[mt][0] = As[(mb + g)     * APW + kp0 + tg];
                af[mt][1] = As[(mb + g + 8) * APW + kp0 + tg];
                af[mt][2] = As[(mb + g)     * APW + kp0 + tg + 4];
                af[mt][3] = As[(mb + g + 8) * APW + kp0 + tg + 4];
            }
#pragma unroll
            for (int nt = 0; nt < 8; nt++) {
                int nb = wn + nt * 8;
                bf[nt][0] = Bs[(kp0 + tg)     * BPW + nb + g];
                bf[nt][1] = Bs[(kp0 + tg + 4) * BPW + nb + g];
            }
#pragma unroll
            for (int mt = 0; mt < 4; mt++)
#pragma unroll
                for (int nt = 0; nt < 8; nt++)
                    mma16(acc[mt][nt], af[mt], bf[nt]);
        }
    }

#pragma unroll
    for (int mt = 0; mt < 4; mt++) {
#pragma unroll
        for (int nt = 0; nt < 8; nt++) {
            int row0 = bm + wm + mt * 16 + g;
            int col  = bn + wn + nt * 8 + tg * 2;
            float b0 = bias ? bias[col]     : 0.f;
            float b1 = bias ? bias[col + 1] : 0.f;
            float v0 = acc[mt][nt][0] + b0;
            float v1 = acc[mt][nt][1] + b1;
            float v2 = acc[mt][nt][2] + b0;
            float v3 = acc[mt][nt][3] + b1;
            if (relu) {
                v0 = fmaxf(v0, 0.f); v1 = fmaxf(v1, 0.f);
                v2 = fmaxf(v2, 0.f); v3 = fmaxf(v3, 0.f);
            }
            if (Ch) {
                int colw = col >> 1;
                int ldw = ldc >> 1;
                if (row0 < M)     Ch[(size_t)row0 * ldw + colw]       = packh(v0, v1);
                if (row0 + 8 < M) Ch[(size_t)(row0 + 8) * ldw + colw] = packh(v2, v3);
            } else {
                if (row0 < M)     *(float2*)(Cf + (size_t)row0 * ldc + col)       = make_float2(v0, v1);
                if (row0 + 8 < M) *(float2*)(Cf + (size_t)(row0 + 8) * ldc + col) = make_float2(v2, v3);
            }
        }
    }
}

__global__ void __launch_bounds__(128) k_gemm_h(
    const unsigned* __restrict__ Ah, int ldaw, const unsigned* __restrict__ Bh, int ldbw,
    const float* __restrict__ bias, float* __restrict__ Cf, unsigned* __restrict__ Ch,
    int ldc, int M, int Kd, int relu)
{
    h_gemm_tile(Ah, ldaw, Bh, ldbw, bias, Cf, Ch, ldc, M, Kd,
                blockIdx.x * 128, blockIdx.y * 128, relu);
}

__global__ void __launch_bounds__(128) k_moe_gemm_h(
    const unsigned* __restrict__ Abase, const unsigned* __restrict__ Wbase,
    const float* __restrict__ bbase, float* __restrict__ Cf, unsigned* __restrict__ Ch,
    int Kd, int Nn, int relu)
{
    int e = blockIdx.z;
    int cnt = g_cnt[e];
    int bm = blockIdx.x * 128;
    if (bm >= cnt) return;
    int off = g_off[e];
    int kw = Kd >> 1;
    h_gemm_tile(Abase + (size_t)off * kw, kw,
                Wbase + (size_t)e * kw * Nn, Nn,
                bbase + (size_t)e * Nn,
                Cf ? Cf + (size_t)off * Nn : (float*)0,
                Ch ? Ch + (size_t)off * (Nn >> 1) : (unsigned*)0,
                Nn, cnt, Kd, bm, blockIdx.y * 128, relu);
}

// ---------------- fp16 flash attention ----------------
__global__ void __launch_bounds__(256) k_flash(
    const unsigned* __restrict__ Qh, const unsigned* __restrict__ Kh,
    const float* __restrict__ Vg, unsigned* __restrict__ ATh)
{
    extern __shared__ unsigned fsm[];
    unsigned* Ks = fsm;                       // [KC][KSW]
    unsigned* Vs = Ks + KC * KSW;             // [KC/2][VSW]
    unsigned* Ps = Vs + (KC / 2) * VSW;       // [QT][PSW]

    const int bh = blockIdx.y;
    const int b = bh >> 4, h = bh & 15;
    const int q0 = blockIdx.x * QT;
    const int tid = threadIdx.x;
    const int lane = tid & 31;
    const int wid = tid >> 5;
    const int g = lane >> 2;
    const int tg = lane & 3;
    const int wrow = wid * 16;

    const int LDW = Dm / 2;
    const unsigned* Qp = Qh + (size_t)b * Sseq * LDW + h * 32;
    const unsigned* Kp = Kh + (size_t)b * Sseq * LDW + h * 32;
    const float*    Vp = Vg + (size_t)b * Sseq * Dm + h * DHd;

    unsigned qf[4][4];
#pragma unroll
    for (int kt = 0; kt < 4; kt++) {
        int kp0 = kt * 8;
        qf[kt][0] = Qp[(size_t)(q0 + wrow + g)     * LDW + kp0 + tg];
        qf[kt][1] = Qp[(size_t)(q0 + wrow + g + 8) * LDW + kp0 + tg];
        qf[kt][2] = Qp[(size_t)(q0 + wrow + g)     * LDW + kp0 + tg + 4];
        qf[kt][3] = Qp[(size_t)(q0 + wrow + g + 8) * LDW + kp0 + tg + 4];
    }

    float oacc[8][4];
#pragma unroll
    for (int i = 0; i < 8; i++)
#pragma unroll
        for (int j = 0; j < 4; j++) oacc[i][j] = 0.f;
    float m0 = -1e30f, m1 = -1e30f, l0 = 0.f, l1 = 0.f;

    for (int c = 0; c < Sseq / KC; c++) {
        int kc0 = c * KC;
#pragma unroll
        for (int i = 0; i < 2; i++) {
            int idx = tid + i * 256;
            int r = idx >> 3, q4 = (idx & 7) << 2;
            uint4 w = *(const uint4*)(Kp + (size_t)(kc0 + r) * LDW + q4);
            *(uint4*)&Ks[r * KSW + q4] = w;
        }
#pragma unroll
        for (int i = 0; i < 2; i++) {
            int idx = tid + i * 256;
            int kcp = idx >> 4, c4 = (idx & 15) << 2;
            const float* v0 = Vp + (size_t)(kc0 + 2 * kcp) * Dm + c4;
            const float* v1 = v0 + Dm;
            float4 a = *(const float4*)v0;
            float4 bb = *(const float4*)v1;
            uint4 w;
            w.x = packh(a.x, bb.x); w.y = packh(a.y, bb.y);
            w.z = packh(a.z, bb.z); w.w = packh(a.w, bb.w);
            *(uint4*)&Vs[kcp * VSW + c4] = w;
        }
        __syncthreads();

        float sacc[8][4];
#pragma unroll
        for (int i = 0; i < 8; i++)
#pragma unroll
            for (int j = 0; j < 4; j++) sacc[i][j] = 0.f;
#pragma unroll
        for (int kt = 0; kt < 4; kt++) {
            int kp0 = kt * 8;
            unsigned bf[8][2];
#pragma unroll
            for (int nt = 0; nt < 8; nt++) {
                bf[nt][0] = Ks[(nt * 8 + g) * KSW + kp0 + tg];
                bf[nt][1] = Ks[(nt * 8 + g) * KSW + kp0 + tg + 4];
            }
#pragma unroll
            for (int nt = 0; nt < 8; nt++)
                mma16(sacc[nt], qf[kt], bf[nt]);
        }

        float mx0 = -1e30f, mx1 = -1e30f;
#pragma unroll
        for (int nt = 0; nt < 8; nt++) {
            sacc[nt][0] *= 0.125f; sacc[nt][1] *= 0.125f;
            sacc[nt][2] *= 0.125f; sacc[nt][3] *= 0.125f;
            mx0 = fmaxf(mx0, fmaxf(sacc[nt][0], sacc[nt][1]));
            mx1 = fmaxf(mx1, fmaxf(sacc[nt][2], sacc[nt][3]));
        }
        mx0 = fmaxf(mx0, __shfl_xor_sync(0xffffffff, mx0, 1));
        mx0 = fmaxf(mx0, __shfl_xor_sync(0xffffffff, mx0, 2));
        mx1 = fmaxf(mx1, __shfl_xor_sync(0xffffffff, mx1, 1));
        mx1 = fmaxf(mx1, __shfl_xor_sync(0xffffffff, mx1, 2));
        float nm0 = fmaxf(m0, mx0), nm1 = fmaxf(m1, mx1);
        float sc0 = __expf(m0 - nm0), sc1 = __expf(m1 - nm1);
        float ps0 = 0.f, ps1 = 0.f;
#pragma unroll
        for (int nt = 0; nt < 8; nt++) {
            float p00 = __expf(sacc[nt][0] - nm0);
            float p01 = __expf(sacc[nt][1] - nm0);
            float p10 = __expf(sacc[nt][2] - nm1);
            float p11 = __expf(sacc[nt][3] - nm1);
            ps0 += p00 + p01; ps1 += p10 + p11;
            int cw = nt * 4 + tg;
            Ps[(wrow + g)     * PSW + cw] = packh(p00, p01);
            Ps[(wrow + g + 8) * PSW + cw] = packh(p10, p11);
        }
        ps0 += __shfl_xor_sync(0xffffffff, ps0, 1);
        ps0 += __shfl_xor_sync(0xffffffff, ps0, 2);
        ps1 += __shfl_xor_sync(0xffffffff, ps1, 1);
        ps1 += __shfl_xor_sync(0xffffffff, ps1, 2);
        l0 = l0 * sc0 + ps0; l1 = l1 * sc1 + ps1;
        m0 = nm0; m1 = nm1;
#pragma unroll
        for (int nt = 0; nt < 8; nt++) {
            oacc[nt][0] *= sc0; oacc[nt][1] *= sc0;
            oacc[nt][2] *= sc1; oacc[nt][3] *= sc1;
        }
        __syncwarp();

#pragma unroll
        for (int kt = 0; kt < 4; kt++) {
            int kp0 = kt * 8;
            unsigned af[4];
            af[0] = Ps[(wrow + g)     * PSW + kp0 + tg];
            af[1] = Ps[(wrow + g + 8) * PSW + kp0 + tg];
            af[2] = Ps[(wrow + g)     * PSW + kp0 + tg + 4];
            af[3] = Ps[(wrow + g + 8) * PSW + kp0 + tg + 4];
            unsigned bf[8][2];
#pragma unroll
            for (int nt = 0; nt < 8; nt++) {
                bf[nt][0] = Vs[(kp0 + tg)     * VSW + nt * 8 + g];
                bf[nt][1] = Vs[(kp0 + tg + 4) * VSW + nt * 8 + g];
            }
#pragma unroll
            for (int nt = 0; nt < 8; nt++)
                mma16(oacc[nt], af, bf[nt]);
        }
        __syncthreads();
    }

    float inv0 = 1.f / l0, inv1 = 1.f / l1;
    const size_t r0 = (size_t)(b * Sseq + q0 + wrow + g) * LDW;
    const size_t r1 = (size_t)(b * Sseq + q0 + wrow + g + 8) * LDW;
#pragma unroll
    for (int nt = 0; nt < 8; nt++) {
        int colw = h * 32 + nt * 4 + tg;
        ATh[r0 + colw] = packh(oacc[nt][0] * inv0, oacc[nt][1] * inv0);
        ATh[r1 + colw] = packh(oacc[nt][2] * inv1, oacc[nt][3] * inv1);
    }
}

// ---------------- layernorm(residual) with optional fp16 output ----------------
__global__ void k_ln_res(const float* __restrict__ X, const float* __restrict__ R,
                         const float* __restrict__ gw, const float* __restrict__ bw,
                         float* __restrict__ O, unsigned* __restrict__ Oh)
{
    int t = blockIdx.x, tid = threadIdx.x;
    const float2* xp = (const float2*)(X + (size_t)t * Dm);
    const float2* rp = (const float2*)(R + (size_t)t * Dm);
    float2 v[2]; float s = 0.f;
#pragma unroll
    for (int i = 0; i < 2; i++) {
        int d2 = tid + i * 256;
        float2 a = xp[d2], b = rp[d2];
        v[i].x = a.x + b.x; v[i].y = a.y + b.y;
        s += v[i].x + v[i].y;
    }
    __shared__ float red[256];
    red[tid] = s; __syncthreads();
    for (int st = 128; st > 0; st >>= 1) {
        if (tid < st) red[tid] += red[tid + st];
        __syncthreads();
    }
    float mean = red[0] * (1.f / Dm);
    __syncthreads();
    float s2 = 0.f;
#pragma unroll
    for (int i = 0; i < 2; i++) {
        float dx = v[i].x - mean, dy = v[i].y - mean;
        s2 += dx * dx + dy * dy;
    }
    red[tid] = s2; __syncthreads();
    for (int st = 128; st > 0; st >>= 1) {
        if (tid < st) red[tid] += red[tid + st];
        __syncthreads();
    }
    float rstd = rsqrtf(red[0] * (1.f / Dm) + 1e-5f);
    float2* op = (float2*)(O + (size_t)t * Dm);
    const float2* gp = (const float2*)gw;
    const float2* bp = (const float2*)bw;
#pragma unroll
    for (int i = 0; i < 2; i++) {
        int d2 = tid + i * 256;
        float2 gg = gp[d2], bb = bp[d2];
        float ox = (v[i].x - mean) * rstd * gg.x + bb.x;
        float oy = (v[i].y - mean) * rstd * gg.y + bb.y;
        op[d2] = make_float2(ox, oy);
        if (Oh) Oh[(size_t)t * (Dm / 2) + d2] = packh(ox, oy);
    }
}

// ---------------- fused MoE combine + layernorm ----------------
__global__ void k_moe_out(const float* __restrict__ X2,
                          const float* __restrict__ gw, const float* __restrict__ bw,
                          float* __restrict__ O)
{
    int t = blockIdx.x, tid = threadIdx.x;
    int p0 = g_tok_pos[t * 2], p1 = g_tok_pos[t * 2 + 1];
    float w0 = g_tok_g[t * 2], w1 = g_tok_g[t * 2 + 1];
    const float* xp = X2 + (size_t)t * Dm;
    const float* y0 = g_YG + (size_t)p0 * Dm;
    const float* y1 = g_YG + (size_t)p1 * Dm;
    float v[4]; float s = 0.f;
#pragma unroll
    for (int i = 0; i < 4; i++) {
        int d = tid + i * 256;
        v[i] = xp[d] + w0 * y0[d] + w1 * y1[d];
        s += v[i];
    }
    __shared__ float red[256];
    red[tid] = s; __syncthreads();
    for (int st = 128; st > 0; st >>= 1) {
        if (tid < st) red[tid] += red[tid + st];
        __syncthreads();
    }
    float mean = red[0] * (1.f / Dm);
    __syncthreads();
    float s2 = 0.f;
#pragma unroll
    for (int i = 0; i < 4; i++) { float dd = v[i] - mean; s2 += dd * dd; }
    red[tid] = s2; __syncthreads();
    for (int st = 128; st > 0; st >>= 1) {
        if (tid < st) red[tid] += red[tid + st];
        __syncthreads();
    }
    float rstd = rsqrtf(red[0] * (1.f / Dm) + 1e-5f);
    float* op = O + (size_t)t * Dm;
#pragma unroll
    for (int i = 0; i < 4; i++) {
        int d = tid + i * 256;
        op[d] = (v[i] - mean) * rstd * gw[d] + bw[d];
    }
}

// ---------------- MoE routing / dispatch ----------------
__global__ void k_moe_init()
{
    int tid = threadIdx.x;
    if (tid < Ee) { g_cnt[tid] = 0; g_cur[tid] = 0; }
}

__global__ void k_router(const float* __restrict__ X,
                         const float* __restrict__ rw,
                         const float* __restrict__ rb,
                         int mode)
{
    int t = blockIdx.x, tid = threadIdx.x;
    const float* xp = X + (size_t)t * Dm;
    float loc[Ee];
#pragma unroll
    for (int e = 0; e < Ee; e++) loc[e] = 0.f;
    for (int d = tid; d < Dm; d += 256) {
        float xv = xp[d];
#pragma unroll
        for (int e = 0; e < Ee; e++) loc[e] += xv * rw[d * Ee + e];
    }
    __shared__ float red[256 * Ee];
#pragma unroll
    for (int e = 0; e < Ee; e++) red[tid * Ee + e] = loc[e];
    __syncthreads();
    for (int st = 128; st > 0; st >>= 1) {
        if (tid < st)
#pragma unroll
            for (int e = 0; e < Ee; e++)
                red[tid * Ee + e] += red[(tid + st) * Ee + e];
        __syncthreads();
    }
    if (tid == 0) {
        float lg[Ee], mx = -1e30f;
#pragma unroll
        for (int e = 0; e < Ee; e++) { lg[e] = red[e] + rb[e]; mx = fmaxf(mx, lg[e]); }
        float sm = 0.f;
#pragma unroll
        for (int e = 0; e < Ee; e++) { lg[e] = expf(lg[e] - mx); sm += lg[e]; }
        float inv = 1.f / sm;
#pragma unroll
        for (int e = 0; e < Ee; e++) lg[e] *= inv;
        int e0 = 0;
#pragma unroll
        for (int e = 1; e < Ee; e++) if (lg[e] > lg[e0]) e0 = e;
        int e1 = -1;
#pragma unroll
        for (int e = 0; e < Ee; e++)
            if (e != e0 && (e1 < 0 || lg[e] > lg[e1])) e1 = e;
        if (mode == 0) {
            float g0 = lg[e0], g1 = lg[e1], gs = g0 + g1;
            g_tok_e[t * 2] = e0;  g_tok_e[t * 2 + 1] = e1;
            g_tok_g[t * 2] = g0 / gs; g_tok_g[t * 2 + 1] = g1 / gs;
            atomicAdd(&g_cnt[e0], 1); atomicAdd(&g_cnt[e1], 1);
        } else {
#pragma unroll
            for (int e = 0; e < Ee; e++) g_auxp[t * Ee + e] = lg[e];
            g_auxi[t * 2] = e0; g_auxi[t * 2 + 1] = e1;
        }
    }
}

__global__ void k_offsets()
{
    if (threadIdx.x == 0) {
        int acc = 0;
        for (int e = 0; e < Ee; e++) {
            g_off[e] = acc;
            acc += ((g_cnt[e] + 127) >> 7) << 7;
        }
        g_off[Ee] = acc;
    }
}

__global__ void k_gather(const float* __restrict__ X)
{
    int t = blockIdx.x, tid = threadIdx.x;
    __shared__ int spos[TOPK];
    if (tid == 0) {
#pragma unroll
        for (int k = 0; k < TOPK; k++) {
            int e = g_tok_e[t * 2 + k];
            int p = g_off[e] + atomicAdd(&g_cur[e], 1);
            spos[k] = p;
            g_tok_pos[t * 2 + k] = p;
        }
    }
    __syncthreads();
    float4 v = reinterpret_cast<const float4*>(X + (size_t)t * Dm)[tid];
    uint2 w = make_uint2(packh(v.x, v.y), packh(v.z, v.w));
#pragma unroll
    for (int k = 0; k < TOPK; k++)
        reinterpret_cast<uint2*>(g_XGh + (size_t)spos[k] * (Dm / 2))[tid] = w;
}

__global__ void k_aux_final(float* __restrict__ out)
{
    int tid = threadIdx.x;
    float imp[Ee];
#pragma unroll
    for (int e = 0; e < Ee; e++) imp[e] = 0.f;
    for (int t = tid; t < Ntok; t += 256)
#pragma unroll
        for (int e = 0; e < Ee; e++) imp[e] += g_auxp[t * Ee + e];
    float ld[Ee];
#pragma unroll
    for (int e = 0; e < Ee; e++) ld[e] = 0.f;
    for (int i = tid; i < Ntok * TOPK; i += 256) ld[g_auxi[i]] += 1.f;

    __shared__ float red[256 * Ee];
    __shared__ float simp[Ee];
#pragma unroll
    for (int e = 0; e < Ee; e++) red[tid * Ee + e] = imp[e];
    __syncthreads();
    for (int st = 128; st > 0; st >>= 1) {
        if (tid < st)
#pragma unroll
            for (int e = 0; e < Ee; e++)
                red[tid * Ee + e] += red[(tid + st) * Ee + e];
        __syncthreads();
    }
    if (tid == 0)
#pragma unroll
        for (int e = 0; e < Ee; e++) simp[e] = red[e];
    __syncthreads();
#pragma unroll
    for (int e = 0; e < Ee; e++) red[tid * Ee + e] = ld[e];
    __syncthreads();
    for (int st = 128; st > 0; st >>= 1) {
        if (tid < st)
#pragma unroll
            for (int e = 0; e < Ee; e++)
                red[tid * Ee + e] += red[(tid + st) * Ee + e];
        __syncthreads();
    }
    if (tid == 0) {
        float aux = 0.f;
#pragma unroll
        for (int e = 0; e < Ee; e++)
            aux += (simp[e] / (float)Ntok) * (red[e] / (float)(Ntok * TOPK));
        out[0] = (float)Ee * aux;
    }
}

// ---------------- host orchestration ----------------
extern "C" void kernel_launch(void* const* d_in, const int* in_sizes, int n_in,
                              void* d_out, int out_size)
{
    (void)in_sizes; (void)n_in;
    const float* x     = (const float*)d_in[0];
    const float* enc   = (const float*)d_in[1];
    const float* sa_wq = (const float*)d_in[2];
    const float* sa_bq = (const float*)d_in[3];
    const float* sa_wk = (const float*)d_in[4];
    const float* sa_bk = (const float*)d_in[5];
    const float* sa_wv = (const float*)d_in[6];
    const float* sa_bv = (const float*)d_in[7];
    const float* sa_wo = (const float*)d_in[8];
    const float* sa_bo = (const float*)d_in[9];
    const float* ca_wq = (const float*)d_in[10];
    const float* ca_bq = (const float*)d_in[11];
    const float* ca_wk = (const float*)d_in[12];
    const float* ca_bk = (const float*)d_in[13];
    const float* ca_wv = (const float*)d_in[14];
    const float* ca_bv = (const float*)d_in[15];
    const float* ca_wo = (const float*)d_in[16];
    const float* ca_bo = (const float*)d_in[17];
    const float* n1_g  = (const float*)d_in[18];
    const float* n1_b  = (const float*)d_in[19];
    const float* n2_g  = (const float*)d_in[20];
    const float* n2_b  = (const float*)d_in[21];
    const float* n3_g  = (const float*)d_in[22];
    const float* n3_b  = (const float*)d_in[23];
    const float* r_w   = (const float*)d_in[24];
    const float* r_b   = (const float*)d_in[25];
    const float* e_w1  = (const float*)d_in[26];
    const float* e_b1  = (const float*)d_in[27];
    const float* e_w2  = (const float*)d_in[28];
    const float* e_b2  = (const float*)d_in[29];

    void *pV, *pPR, *pX1, *pX2, *pYG;
    void *pQh, *pKh, *pxh, *pench, *pX1h, *pATh, *pwh, *pe1h, *pe2h, *pXGh, *pHBh;
    cudaGetSymbolAddress(&pV,  g_V);
    cudaGetSymbolAddress(&pPR, g_PR);
    cudaGetSymbolAddress(&pX1, g_X1);
    cudaGetSymbolAddress(&pX2, g_X2);
    cudaGetSymbolAddress(&pYG, g_YG);
    cudaGetSymbolAddress(&pQh,  g_Qh);
    cudaGetSymbolAddress(&pKh,  g_Kh);
    cudaGetSymbolAddress(&pxh,  g_xh);
    cudaGetSymbolAddress(&pench, g_ench);
    cudaGetSymbolAddress(&pX1h, g_X1h);
    cudaGetSymbolAddress(&pATh, g_ATh);
    cudaGetSymbolAddress(&pwh,  g_wh);
    cudaGetSymbolAddress(&pe1h, g_e1h);
    cudaGetSymbolAddress(&pe2h, g_e2h);
    cudaGetSymbolAddress(&pXGh, g_XGh);
    cudaGetSymbolAddress(&pHBh, g_HBh);
    float* V  = (float*)pV;
    float* PR = (float*)pPR; float* X1 = (float*)pX1; float* X2 = (float*)pX2;
    float* YG = (float*)pYG;
    unsigned* Qh   = (unsigned*)pQh;
    unsigned* Kh   = (unsigned*)pKh;
    unsigned* xh   = (unsigned*)pxh;
    unsigned* ench = (unsigned*)pench;
    unsigned* X1h  = (unsigned*)pX1h;
    unsigned* ATh  = (unsigned*)pATh;
    unsigned* wh   = (unsigned*)pwh;
    unsigned* e1h  = (unsigned*)pe1h;
    unsigned* e2h  = (unsigned*)pe2h;
    unsigned* XGh  = (unsigned*)pXGh;
    unsigned* HBh  = (unsigned*)pHBh;
    float* out = (float*)d_out;

    static int smem_set = 0;
    if (!smem_set) {
        cudaFuncSetAttribute(k_flash, cudaFuncAttributeMaxDynamicSharedMemorySize, FLASH_SMEM);
        cudaFuncSetAttribute(k_gemm_h, cudaFuncAttributeMaxDynamicSharedMemorySize, H_SMEM);
        cudaFuncSetAttribute(k_moe_gemm_h, cudaFuncAttributeMaxDynamicSharedMemorySize, H_SMEM);
        smem_set = 1;
    }

    dim3 gblk(128);
    dim3 blk(256);
    dim3 gProj(Ntok / 128, Dm / 128);
    dim3 gFlash(Sseq / QT, Bbat * Hh);
    const int WSTRIDE = (Dm / 2) * Dm;

    // ---- fp16 conversions ----
    {
        int nq = Ntok * Dm / 4;
        k_cvtA<<<(nq + 255) / 256, 256>>>(x, xh, nq);
        k_cvtA<<<(nq + 255) / 256, 256>>>(enc, ench, nq);
        int bw = ((Dm / 2) * (Dm / 4) + 255) / 256;
        k_cvtB<<<bw, 256>>>(sa_wq, wh + 0 * WSTRIDE, Dm, Dm);
        k_cvtB<<<bw, 256>>>(sa_wk, wh + 1 * WSTRIDE, Dm, Dm);
        k_cvtB<<<bw, 256>>>(sa_wv, wh + 2 * WSTRIDE, Dm, Dm);
        k_cvtB<<<bw, 256>>>(sa_wo, wh + 3 * WSTRIDE, Dm, Dm);
        k_cvtB<<<bw, 256>>>(ca_wq, wh + 4 * WSTRIDE, Dm, Dm);
        k_cvtB<<<bw, 256>>>(ca_wk, wh + 5 * WSTRIDE, Dm, Dm);
        k_cvtB<<<bw, 256>>>(ca_wv, wh + 6 * WSTRIDE, Dm, Dm);
        k_cvtB<<<bw, 256>>>(ca_wo, wh + 7 * WSTRIDE, Dm, Dm);
        int b1 = ((Ee * Dm / 2) * (Ff / 4) + 255) / 256;
        k_cvtB<<<b1, 256>>>(e_w1, e1h, Ee * Dm, Ff);
        int b2 = ((Ee * Ff / 2) * (Dm / 4) + 255) / 256;
        k_cvtB<<<b2, 256>>>(e_w2, e2h, Ee * Ff, Dm);
    }

    // ---- self attention (Q,K emitted fp16; V f32) ----
    k_gemm_h<<<gProj, gblk, H_SMEM>>>(xh, Dm/2, wh + 0*WSTRIDE, Dm, sa_bq, (float*)0, Qh, Dm, Ntok, Dm, 0);
    k_gemm_h<<<gProj, gblk, H_SMEM>>>(xh, Dm/2, wh + 1*WSTRIDE, Dm, sa_bk, (float*)0, Kh, Dm, Ntok, Dm, 0);
    k_gemm_h<<<gProj, gblk, H_SMEM>>>(xh, Dm/2, wh + 2*WSTRIDE, Dm, sa_bv, V, (unsigned*)0, Dm, Ntok, Dm, 0);
    k_flash<<<gFlash, blk, FLASH_SMEM>>>(Qh, Kh, V, ATh);
    k_gemm_h<<<gProj, gblk, H_SMEM>>>(ATh, Dm/2, wh + 3*WSTRIDE, Dm, sa_bo, PR, (unsigned*)0, Dm, Ntok, Dm, 0);
    k_ln_res<<<Ntok, blk>>>(x, PR, n1_g, n1_b, X1, X1h);

    // ---- cross attention ----
    k_gemm_h<<<gProj, gblk, H_SMEM>>>(X1h,  Dm/2, wh + 4*WSTRIDE, Dm, ca_bq, (float*)0, Qh, Dm, Ntok, Dm, 0);
    k_gemm_h<<<gProj, gblk, H_SMEM>>>(ench, Dm/2, wh + 5*WSTRIDE, Dm, ca_bk, (float*)0, Kh, Dm, Ntok, Dm, 0);
    k_gemm_h<<<gProj, gblk, H_SMEM>>>(ench, Dm/2, wh + 6*WSTRIDE, Dm, ca_bv, V, (unsigned*)0, Dm, Ntok, Dm, 0);
    k_flash<<<gFlash, blk, FLASH_SMEM>>>(Qh, Kh, V, ATh);
    k_gemm_h<<<gProj, gblk, H_SMEM>>>(ATh, Dm/2, wh + 7*WSTRIDE, Dm, ca_bo, PR, (unsigned*)0, Dm, Ntok, Dm, 0);
    k_ln_res<<<Ntok, blk>>>(X1, PR, n2_g, n2_b, X2, (unsigned*)0);

    // ---- MoE (sparse top-2 dispatch) ----
    k_moe_init<<<1, blk>>>();
    k_router<<<Ntok, blk>>>(X2, r_w, r_b, 0);
    k_offsets<<<1, 1>>>();
    k_gather<<<Ntok, blk>>>(X2);
    k_moe_gemm_h<<<dim3(Ntok / 128, Ff / 128, Ee), gblk, H_SMEM>>>(XGh, e1h, e_b1, (float*)0, HBh, Dm, Ff, 1);
    k_moe_gemm_h<<<dim3(Ntok / 128, Dm / 128, Ee), gblk, H_SMEM>>>(HBh, e2h, e_b2, YG, (unsigned*)0, Ff, Dm, 0);
    k_moe_out<<<Ntok, blk>>>(X2, n3_g, n3_b, out);

    // ---- aux loss (router recompute on OUTPUT, per reference) ----
    if (out_size > Ntok * Dm) {
        k_router<<<Ntok, blk>>>(out, r_w, r_b, 1);
        k_aux_final<<<1, blk>>>(out + (out_size - 1));
    }
}

// round 12
// speedup vs baseline: 1.6813x; 1.0334x over previous
#include <cuda_runtime.h>
#include <math.h>
#include <stdint.h>

// ---------------- problem constants ----------------
#define Dm      1024
#define Hh      16
#define DHd     64
#define Ff      4096
#define Ee      8
#define TOPK    2
#define Bbat    2
#define Sseq    2048
#define Ntok    4096
#define NKCAP   16384

// fp16 GEMM tiling: 128x128x64 tile, 128 threads (4 warps of 64x64)
// A smem [m][kw] pad 36, B smem [n][kw] pad 36 (K-major both sides)
#define APW 36
#define H_ASZ (128 * APW)
#define H_STG (2 * H_ASZ)
#define H_NSTAGE 3
#define H_SMEM (H_NSTAGE * H_STG * 4)

// fp16 flash tiling
#define QT    128
#define KC    64
#define KSW   36          // Ks [key][kw]
#define VSW   72          // Vs [kc word][dh]
#define PSW   36          // Ps [q][kc words]
#define FLASH_SMEM ((KC*KSW + (KC/2)*VSW + QT*PSW) * 4)

// ---------------- device scratch ----------------
__device__ float g_V [Ntok * Dm];
__device__ float g_PR[Ntok * Dm];
__device__ float g_X1[Ntok * Dm];
__device__ float g_X2[Ntok * Dm];
__device__ float g_YG[(size_t)NKCAP * Dm];

__device__ unsigned g_Qh  [Ntok * Dm / 2];
__device__ unsigned g_Kh  [Ntok * Dm / 2];
__device__ unsigned g_xh  [Ntok * Dm / 2];
__device__ unsigned g_ench[Ntok * Dm / 2];
__device__ unsigned g_X1h [Ntok * Dm / 2];
__device__ unsigned g_ATh [Ntok * Dm / 2];
__device__ unsigned g_wh  [8][(Dm / 2) * Dm];           // [N][Kw] K-major
__device__ unsigned g_e1h [(size_t)Ee * (Dm / 2) * Ff]; // per-expert [Ff][Dm/2]
__device__ unsigned g_e2h [(size_t)Ee * (Ff / 2) * Dm]; // per-expert [Dm][Ff/2]
__device__ unsigned g_XGh [(size_t)NKCAP * Dm / 2];
__device__ unsigned g_HBh [(size_t)NKCAP * Ff / 2];

__device__ int   g_tok_e[Ntok * TOPK];
__device__ float g_tok_g[Ntok * TOPK];
__device__ int   g_tok_pos[Ntok * TOPK];
__device__ int   g_cnt[Ee];
__device__ int   g_cur[Ee];
__device__ int   g_off[Ee + 1];
__device__ float g_auxp[Ntok * Ee];
__device__ int   g_auxi[Ntok * TOPK];

// ---------------- helpers ----------------
__device__ __forceinline__ unsigned packh(float lo, float hi) {
    unsigned r;
    asm("cvt.rn.f16x2.f32 %0, %1, %2;" : "=r"(r) : "f"(hi), "f"(lo));
    return r;
}

__device__ __forceinline__ void mma16(float* c, const unsigned* a, const unsigned* b) {
    asm volatile(
        "mma.sync.aligned.m16n8k16.row.col.f32.f16.f16.f32 "
        "{%0,%1,%2,%3},{%4,%5,%6,%7},{%8,%9},{%0,%1,%2,%3};\n"
        : "+f"(c[0]), "+f"(c[1]), "+f"(c[2]), "+f"(c[3])
        : "r"(a[0]), "r"(a[1]), "r"(a[2]), "r"(a[3]), "r"(b[0]), "r"(b[1]));
}

__device__ __forceinline__ void ldsm4(unsigned* r, const unsigned* p) {
    unsigned a = (unsigned)__cvta_generic_to_shared(p);
    asm volatile("ldmatrix.sync.aligned.m8n8.x4.shared.b16 {%0,%1,%2,%3}, [%4];"
                 : "=r"(r[0]), "=r"(r[1]), "=r"(r[2]), "=r"(r[3]) : "r"(a));
}

__device__ __forceinline__ void cp16(void* smem, const void* gmem, bool pred) {
    unsigned saddr = (unsigned)__cvta_generic_to_shared(smem);
    int sz = pred ? 16 : 0;
    asm volatile("cp.async.ca.shared.global [%0], [%1], 16, %2;\n"
                 :: "r"(saddr), "l"(gmem), "r"(sz));
}
__device__ __forceinline__ void cp_commit() {
    asm volatile("cp.async.commit_group;\n");
}
__device__ __forceinline__ void cp_wait1() {
    asm volatile("cp.async.wait_group 1;\n" ::: "memory");
}

// ---------------- fp16 conversions ----------------
// A-style: [M][K] f32 -> [M][K/2] words
__global__ void k_cvtA(const float* __restrict__ src, unsigned* __restrict__ dst, int nquads)
{
    int i = blockIdx.x * blockDim.x + threadIdx.x;
    if (i >= nquads) return;
    float4 v = ((const float4*)src)[i];
    ((uint2*)dst)[i] = make_uint2(packh(v.x, v.y), packh(v.z, v.w));
}

// transpose-pack: [K][N] f32 -> [N][K/2] words (word(n,kp) = pack(B[2kp][n], B[2kp+1][n]))
// grid (K/64, N/64, nmat), block 256
__global__ void k_cvtBT(const float* __restrict__ src, unsigned* __restrict__ dst, int K, int N)
{
    __shared__ float sm[64][65];
    src += (size_t)blockIdx.z * K * N;
    dst += (size_t)blockIdx.z * N * (K >> 1);
    int k0 = blockIdx.x * 64, n0 = blockIdx.y * 64;
    int tid = threadIdx.x;
#pragma unroll
    for (int i = 0; i < 4; i++) {
        int q = tid + i * 256;
        int r = q >> 4, c4 = (q & 15) << 2;
        float4 v = *(const float4*)(src + (size_t)(k0 + r) * N + n0 + c4);
        sm[r][c4] = v.x; sm[r][c4 + 1] = v.y; sm[r][c4 + 2] = v.z; sm[r][c4 + 3] = v.w;
    }
    __syncthreads();
    int kw = K >> 1;
#pragma unroll
    for (int i = 0; i < 8; i++) {
        int w = tid + i * 256;
        int n = w >> 5, kp = w & 31;
        dst[(size_t)(n0 + n) * kw + (k0 >> 1) + kp] = packh(sm[2 * kp][n], sm[2 * kp + 1][n]);
    }
}

// ---------------- fp16 GEMM: 128x128x64 tile, 3-stage cp.async, ldmatrix frags ----------------
__device__ __forceinline__ void h_stage(
    unsigned* As, unsigned* Bs,
    const unsigned* __restrict__ Ah, int ldaw,
    const unsigned* __restrict__ Bh, int ldbw,
    int bm, int bn, int kw0, int M, int tid)
{
#pragma unroll
    for (int i = 0; i < 8; i++) {
        int c = tid + i * 128;
        int r = c >> 3, cw = (c & 7) << 2;
        bool p = (bm + r) < M;
        const unsigned* src = Ah + (size_t)(p ? (bm + r) : 0) * ldaw + kw0 + cw;
        cp16(&As[r * APW + cw], src, p);
    }
#pragma unroll
    for (int i = 0; i < 8; i++) {
        int c = tid + i * 128;
        int r = c >> 3, cw = (c & 7) << 2;
        cp16(&Bs[r * APW + cw], Bh + (size_t)(bn + r) * ldbw + kw0 + cw, true);
    }
}

__device__ __forceinline__ void h_gemm_tile(
    const unsigned* __restrict__ Ah, int ldaw,
    const unsigned* __restrict__ Bh, int ldbw,
    const float* __restrict__ bias,
    float* __restrict__ Cf, unsigned* __restrict__ Ch, int ldc,
    int M, int Kd, int bm, int bn, int relu)
{
    extern __shared__ unsigned smp[];

    const int tid  = threadIdx.x;
    const int lane = tid & 31;
    const int wid  = tid >> 5;
    const int wm = (wid >> 1) * 64;
    const int wn = (wid & 1) * 64;
    const int g  = lane >> 2;
    const int tg = lane & 3;
    const int arow = lane & 15, acol = (lane >> 4) << 2;              // A/Ps ldmatrix addr
    const int brow = ((lane >> 4) << 3) + (lane & 7);                 // B ldmatrix addr
    const int bcol = ((lane >> 3) & 1) << 2;

    float acc[4][8][4];
#pragma unroll
    for (int i = 0; i < 4; i++)
#pragma unroll
        for (int j = 0; j < 8; j++)
#pragma unroll
            for (int q = 0; q < 4; q++) acc[i][j][q] = 0.f;

    const int T = Kd / 64;

    h_stage(smp, smp + H_ASZ, Ah, ldaw, Bh, ldbw, bm, bn, 0, M, tid);
    cp_commit();
    h_stage(smp + H_STG, smp + H_STG + H_ASZ, Ah, ldaw, Bh, ldbw, bm, bn, 32, M, tid);
    cp_commit();

    for (int t = 0; t < T; t++) {
        cp_wait1();
        __syncthreads();

        if (t + 2 < T) {
            unsigned* dst = smp + ((t + 2) % H_NSTAGE) * H_STG;
            h_stage(dst, dst + H_ASZ, Ah, ldaw, Bh, ldbw, bm, bn, (t + 2) * 32, M, tid);
        }
        cp_commit();

        const unsigned* As = smp + (t % H_NSTAGE) * H_STG;
        const unsigned* Bs = As + H_ASZ;

#pragma unroll
        for (int ks = 0; ks < 4; ks++) {
            const int kp0 = ks * 8;
            unsigned af[4][4], bq[4][4];
#pragma unroll
            for (int mt = 0; mt < 4; mt++)
                ldsm4(af[mt], As + (wm + mt * 16 + arow) * APW + kp0 + acol);
#pragma unroll
            for (int np = 0; np < 4; np++)
                ldsm4(bq[np], Bs + (wn + np * 16 + brow) * APW + kp0 + bcol);
#pragma unroll
            for (int mt = 0; mt < 4; mt++)
#pragma unroll
                for (int np = 0; np < 4; np++) {
                    mma16(acc[mt][2 * np],     af[mt], &bq[np][0]);
                    mma16(acc[mt][2 * np + 1], af[mt], &bq[np][2]);
                }
        }
    }

#pragma unroll
    for (int mt = 0; mt < 4; mt++) {
#pragma unroll
        for (int nt = 0; nt < 8; nt++) {
            int row0 = bm + wm + mt * 16 + g;
            int col  = bn + wn + nt * 8 + tg * 2;
            float b0 = bias ? bias[col]     : 0.f;
            float b1 = bias ? bias[col + 1] : 0.f;
            float v0 = acc[mt][nt][0] + b0;
            float v1 = acc[mt][nt][1] + b1;
            float v2 = acc[mt][nt][2] + b0;
            float v3 = acc[mt][nt][3] + b1;
            if (relu) {
                v0 = fmaxf(v0, 0.f); v1 = fmaxf(v1, 0.f);
                v2 = fmaxf(v2, 0.f); v3 = fmaxf(v3, 0.f);
            }
            if (Ch) {
                int colw = col >> 1;
                int ldw = ldc >> 1;
                if (row0 < M)     Ch[(size_t)row0 * ldw + colw]       = packh(v0, v1);
                if (row0 + 8 < M) Ch[(size_t)(row0 + 8) * ldw + colw] = packh(v2, v3);
            } else {
                if (row0 < M)     *(float2*)(Cf + (size_t)row0 * ldc + col)       = make_float2(v0, v1);
                if (row0 + 8 < M) *(float2*)(Cf + (size_t)(row0 + 8) * ldc + col) = make_float2(v2, v3);
            }
        }
    }
}

__global__ void __launch_bounds__(128) k_gemm_h(
    const unsigned* __restrict__ Ah, int ldaw, const unsigned* __restrict__ Bh, int ldbw,
    const float* __restrict__ bias, float* __restrict__ Cf, unsigned* __restrict__ Ch,
    int ldc, int M, int Kd, int relu)
{
    h_gemm_tile(Ah, ldaw, Bh, ldbw, bias, Cf, Ch, ldc, M, Kd,
                blockIdx.x * 128, blockIdx.y * 128, relu);
}

__global__ void __launch_bounds__(128) k_moe_gemm_h(
    const unsigned* __restrict__ Abase, const unsigned* __restrict__ Wbase,
    const float* __restrict__ bbase, float* __restrict__ Cf, unsigned* __restrict__ Ch,
    int Kd, int Nn, int relu)
{
    int e = blockIdx.z;
    int cnt = g_cnt[e];
    int bm = blockIdx.x * 128;
    if (bm >= cnt) return;
    int off = g_off[e];
    int kw = Kd >> 1;
    h_gemm_tile(Abase + (size_t)off * kw, kw,
                Wbase + (size_t)e * kw * Nn, kw,
                bbase + (size_t)e * Nn,
                Cf ? Cf + (size_t)off * Nn : (float*)0,
                Ch ? Ch + (size_t)off * (Nn >> 1) : (unsigned*)0,
                Nn, cnt, Kd, bm, blockIdx.y * 128, relu);
}

// ---------------- fp16 flash attention (ldmatrix for Ks/Ps) ----------------
__global__ void __launch_bounds__(256) k_flash(
    const unsigned* __restrict__ Qh, const unsigned* __restrict__ Kh,
    const float* __restrict__ Vg, unsigned* __restrict__ ATh)
{
    extern __shared__ unsigned fsm[];
    unsigned* Ks = fsm;                       // [KC][KSW]
    unsigned* Vs = Ks + KC * KSW;             // [KC/2][VSW]
    unsigned* Ps = Vs + (KC / 2) * VSW;       // [QT][PSW]

    const int bh = blockIdx.y;
    const int b = bh >> 4, h = bh & 15;
    const int q0 = blockIdx.x * QT;
    const int tid = threadIdx.x;
    const int lane = tid & 31;
    const int wid = tid >> 5;
    const int g = lane >> 2;
    const int tg = lane & 3;
    const int wrow = wid * 16;
    const int arow = lane & 15, acol = (lane >> 4) << 2;
    const int brow = ((lane >> 4) << 3) + (lane & 7);
    const int bcol = ((lane >> 3) & 1) << 2;

    const int LDW = Dm / 2;
    const unsigned* Qp = Qh + (size_t)b * Sseq * LDW + h * 32;
    const unsigned* Kp = Kh + (size_t)b * Sseq * LDW + h * 32;
    const float*    Vp = Vg + (size_t)b * Sseq * Dm + h * DHd;

    unsigned qf[4][4];
#pragma unroll
    for (int kt = 0; kt < 4; kt++) {
        int kp0 = kt * 8;
        qf[kt][0] = Qp[(size_t)(q0 + wrow + g)     * LDW + kp0 + tg];
        qf[kt][1] = Qp[(size_t)(q0 + wrow + g + 8) * LDW + kp0 + tg];
        qf[kt][2] = Qp[(size_t)(q0 + wrow + g)     * LDW + kp0 + tg + 4];
        qf[kt][3] = Qp[(size_t)(q0 + wrow + g + 8) * LDW + kp0 + tg + 4];
    }

    float oacc[8][4];
#pragma unroll
    for (int i = 0; i < 8; i++)
#pragma unroll
        for (int j = 0; j < 4; j++) oacc[i][j] = 0.f;
    float m0 = -1e30f, m1 = -1e30f, l0 = 0.f, l1 = 0.f;

    for (int c = 0; c < Sseq / KC; c++) {
        int kc0 = c * KC;
#pragma unroll
        for (int i = 0; i < 2; i++) {
            int idx = tid + i * 256;
            int r = idx >> 3, q4 = (idx & 7) << 2;
            uint4 w = *(const uint4*)(Kp + (size_t)(kc0 + r) * LDW + q4);
            *(uint4*)&Ks[r * KSW + q4] = w;
        }
#pragma unroll
        for (int i = 0; i < 2; i++) {
            int idx = tid + i * 256;
            int kcp = idx >> 4, c4 = (idx & 15) << 2;
            const float* v0 = Vp + (size_t)(kc0 + 2 * kcp) * Dm + c4;
            const float* v1 = v0 + Dm;
            float4 a = *(const float4*)v0;
            float4 bb = *(const float4*)v1;
            uint4 w;
            w.x = packh(a.x, bb.x); w.y = packh(a.y, bb.y);
            w.z = packh(a.z, bb.z); w.w = packh(a.w, bb.w);
            *(uint4*)&Vs[kcp * VSW + c4] = w;
        }
        __syncthreads();

        float sacc[8][4];
#pragma unroll
        for (int i = 0; i < 8; i++)
#pragma unroll
            for (int j = 0; j < 4; j++) sacc[i][j] = 0.f;
#pragma unroll
        for (int kt = 0; kt < 4; kt++) {
            int kp0 = kt * 8;
            unsigned bq[4][4];
#pragma unroll
            for (int np = 0; np < 4; np++)
                ldsm4(bq[np], Ks + (np * 16 + brow) * KSW + kp0 + bcol);
#pragma unroll
            for (int np = 0; np < 4; np++) {
                mma16(sacc[2 * np],     qf[kt], &bq[np][0]);
                mma16(sacc[2 * np + 1], qf[kt], &bq[np][2]);
            }
        }

        float mx0 = -1e30f, mx1 = -1e30f;
#pragma unroll
        for (int nt = 0; nt < 8; nt++) {
            sacc[nt][0] *= 0.125f; sacc[nt][1] *= 0.125f;
            sacc[nt][2] *= 0.125f; sacc[nt][3] *= 0.125f;
            mx0 = fmaxf(mx0, fmaxf(sacc[nt][0], sacc[nt][1]));
            mx1 = fmaxf(mx1, fmaxf(sacc[nt][2], sacc[nt][3]));
        }
        mx0 = fmaxf(mx0, __shfl_xor_sync(0xffffffff, mx0, 1));
        mx0 = fmaxf(mx0, __shfl_xor_sync(0xffffffff, mx0, 2));
        mx1 = fmaxf(mx1, __shfl_xor_sync(0xffffffff, mx1, 1));
        mx1 = fmaxf(mx1, __shfl_xor_sync(0xffffffff, mx1, 2));
        float nm0 = fmaxf(m0, mx0), nm1 = fmaxf(m1, mx1);
        float sc0 = __expf(m0 - nm0), sc1 = __expf(m1 - nm1);
        float ps0 = 0.f, ps1 = 0.f;
#pragma unroll
        for (int nt = 0; nt < 8; nt++) {
            float p00 = __expf(sacc[nt][0] - nm0);
            float p01 = __expf(sacc[nt][1] - nm0);
            float p10 = __expf(sacc[nt][2] - nm1);
            float p11 = __expf(sacc[nt][3] - nm1);
            ps0 += p00 + p01; ps1 += p10 + p11;
            int cw = nt * 4 + tg;
            Ps[(wrow + g)     * PSW + cw] = packh(p00, p01);
            Ps[(wrow + g + 8) * PSW + cw] = packh(p10, p11);
        }
        ps0 += __shfl_xor_sync(0xffffffff, ps0, 1);
        ps0 += __shfl_xor_sync(0xffffffff, ps0, 2);
        ps1 += __shfl_xor_sync(0xffffffff, ps1, 1);
        ps1 += __shfl_xor_sync(0xffffffff, ps1, 2);
        l0 = l0 * sc0 + ps0; l1 = l1 * sc1 + ps1;
        m0 = nm0; m1 = nm1;
#pragma unroll
        for (int nt = 0; nt < 8; nt++) {
            oacc[nt][0] *= sc0; oacc[nt][1] *= sc0;
            oacc[nt][2] *= sc1; oacc[nt][3] *= sc1;
        }
        __syncwarp();

#pragma unroll
        for (int kt = 0; kt < 4; kt++) {
            int kp0 = kt * 8;
            unsigned af[4];
            ldsm4(af, Ps + (wrow + arow) * PSW + kp0 + acol);
            unsigned bf[8][2];
#pragma unroll
            for (int nt = 0; nt < 8; nt++) {
                bf[nt][0] = Vs[(kp0 + tg)     * VSW + nt * 8 + g];
                bf[nt][1] = Vs[(kp0 + tg + 4) * VSW + nt * 8 + g];
            }
#pragma unroll
            for (int nt = 0; nt < 8; nt++)
                mma16(oacc[nt], af, bf[nt]);
        }
        __syncthreads();
    }

    float inv0 = 1.f / l0, inv1 = 1.f / l1;
    const size_t r0 = (size_t)(b * Sseq + q0 + wrow + g) * LDW;
    const size_t r1 = (size_t)(b * Sseq + q0 + wrow + g + 8) * LDW;
#pragma unroll
    for (int nt = 0; nt < 8; nt++) {
        int colw = h * 32 + nt * 4 + tg;
        ATh[r0 + colw] = packh(oacc[nt][0] * inv0, oacc[nt][1] * inv0);
        ATh[r1 + colw] = packh(oacc[nt][2] * inv1, oacc[nt][3] * inv1);
    }
}

// ---------------- layernorm(residual) with optional fp16 output ----------------
__global__ void k_ln_res(const float* __restrict__ X, const float* __restrict__ R,
                         const float* __restrict__ gw, const float* __restrict__ bw,
                         float* __restrict__ O, unsigned* __restrict__ Oh)
{
    int t = blockIdx.x, tid = threadIdx.x;
    const float2* xp = (const float2*)(X + (size_t)t * Dm);
    const float2* rp = (const float2*)(R + (size_t)t * Dm);
    float2 v[2]; float s = 0.f;
#pragma unroll
    for (int i = 0; i < 2; i++) {
        int d2 = tid + i * 256;
        float2 a = xp[d2], b = rp[d2];
        v[i].x = a.x + b.x; v[i].y = a.y + b.y;
        s += v[i].x + v[i].y;
    }
    __shared__ float red[256];
    red[tid] = s; __syncthreads();
    for (int st = 128; st > 0; st >>= 1) {
        if (tid < st) red[tid] += red[tid + st];
        __syncthreads();
    }
    float mean = red[0] * (1.f / Dm);
    __syncthreads();
    float s2 = 0.f;
#pragma unroll
    for (int i = 0; i < 2; i++) {
        float dx = v[i].x - mean, dy = v[i].y - mean;
        s2 += dx * dx + dy * dy;
    }
    red[tid] = s2; __syncthreads();
    for (int st = 128; st > 0; st >>= 1) {
        if (tid < st) red[tid] += red[tid + st];
        __syncthreads();
    }
    float rstd = rsqrtf(red[0] * (1.f / Dm) + 1e-5f);
    float2* op = (float2*)(O + (size_t)t * Dm);
    const float2* gp = (const float2*)gw;
    const float2* bp = (const float2*)bw;
#pragma unroll
    for (int i = 0; i < 2; i++) {
        int d2 = tid + i * 256;
        float2 gg = gp[d2], bb = bp[d2];
        float ox = (v[i].x - mean) * rstd * gg.x + bb.x;
        float oy = (v[i].y - mean) * rstd * gg.y + bb.y;
        op[d2] = make_float2(ox, oy);
        if (Oh) Oh[(size_t)t * (Dm / 2) + d2] = packh(ox, oy);
    }
}

// ---------------- fused MoE combine + layernorm ----------------
__global__ void k_moe_out(const float* __restrict__ X2,
                          const float* __restrict__ gw, const float* __restrict__ bw,
                          float* __restrict__ O)
{
    int t = blockIdx.x, tid = threadIdx.x;
    int p0 = g_tok_pos[t * 2], p1 = g_tok_pos[t * 2 + 1];
    float w0 = g_tok_g[t * 2], w1 = g_tok_g[t * 2 + 1];
    const float* xp = X2 + (size_t)t * Dm;
    const float* y0 = g_YG + (size_t)p0 * Dm;
    const float* y1 = g_YG + (size_t)p1 * Dm;
    float v[4]; float s = 0.f;
#pragma unroll
    for (int i = 0; i < 4; i++) {
        int d = tid + i * 256;
        v[i] = xp[d] + w0 * y0[d] + w1 * y1[d];
        s += v[i];
    }
    __shared__ float red[256];
    red[tid] = s; __syncthreads();
    for (int st = 128; st > 0; st >>= 1) {
        if (tid < st) red[tid] += red[tid + st];
        __syncthreads();
    }
    float mean = red[0] * (1.f / Dm);
    __syncthreads();
    float s2 = 0.f;
#pragma unroll
    for (int i = 0; i < 4; i++) { float dd = v[i] - mean; s2 += dd * dd; }
    red[tid] = s2; __syncthreads();
    for (int st = 128; st > 0; st >>= 1) {
        if (tid < st) red[tid] += red[tid + st];
        __syncthreads();
    }
    float rstd = rsqrtf(red[0] * (1.f / Dm) + 1e-5f);
    float* op = O + (size_t)t * Dm;
#pragma unroll
    for (int i = 0; i < 4; i++) {
        int d = tid + i * 256;
        op[d] = (v[i] - mean) * rstd * gw[d] + bw[d];
    }
}

// ---------------- MoE routing / dispatch ----------------
__global__ void k_moe_init()
{
    int tid = threadIdx.x;
    if (tid < Ee) { g_cnt[tid] = 0; g_cur[tid] = 0; }
}

__global__ void k_router(const float* __restrict__ X,
                         const float* __restrict__ rw,
                         const float* __restrict__ rb,
                         int mode)
{
    int t = blockIdx.x, tid = threadIdx.x;
    const float* xp = X + (size_t)t * Dm;
    float loc[Ee];
#pragma unroll
    for (int e = 0; e < Ee; e++) loc[e] = 0.f;
    for (int d = tid; d < Dm; d += 256) {
        float xv = xp[d];
#pragma unroll
        for (int e = 0; e < Ee; e++) loc[e] += xv * rw[d * Ee + e];
    }
    __shared__ float red[256 * Ee];
#pragma unroll
    for (int e = 0; e < Ee; e++) red[tid * Ee + e] = loc[e];
    __syncthreads();
    for (int st = 128; st > 0; st >>= 1) {
        if (tid < st)
#pragma unroll
            for (int e = 0; e < Ee; e++)
                red[tid * Ee + e] += red[(tid + st) * Ee + e];
        __syncthreads();
    }
    if (tid == 0) {
        float lg[Ee], mx = -1e30f;
#pragma unroll
        for (int e = 0; e < Ee; e++) { lg[e] = red[e] + rb[e]; mx = fmaxf(mx, lg[e]); }
        float sm = 0.f;
#pragma unroll
        for (int e = 0; e < Ee; e++) { lg[e] = expf(lg[e] - mx); sm += lg[e]; }
        float inv = 1.f / sm;
#pragma unroll
        for (int e = 0; e < Ee; e++) lg[e] *= inv;
        int e0 = 0;
#pragma unroll
        for (int e = 1; e < Ee; e++) if (lg[e] > lg[e0]) e0 = e;
        int e1 = -1;
#pragma unroll
        for (int e = 0; e < Ee; e++)
            if (e != e0 && (e1 < 0 || lg[e] > lg[e1])) e1 = e;
        if (mode == 0) {
            float g0 = lg[e0], g1 = lg[e1], gs = g0 + g1;
            g_tok_e[t * 2] = e0;  g_tok_e[t * 2 + 1] = e1;
            g_tok_g[t * 2] = g0 / gs; g_tok_g[t * 2 + 1] = g1 / gs;
            atomicAdd(&g_cnt[e0], 1); atomicAdd(&g_cnt[e1], 1);
        } else {
#pragma unroll
            for (int e = 0; e < Ee; e++) g_auxp[t * Ee + e] = lg[e];
            g_auxi[t * 2] = e0; g_auxi[t * 2 + 1] = e1;
        }
    }
}

__global__ void k_offsets()
{
    if (threadIdx.x == 0) {
        int acc = 0;
        for (int e = 0; e < Ee; e++) {
            g_off[e] = acc;
            acc += ((g_cnt[e] + 127) >> 7) << 7;
        }
        g_off[Ee] = acc;
    }
}

__global__ void k_gather(const float* __restrict__ X)
{
    int t = blockIdx.x, tid = threadIdx.x;
    __shared__ int spos[TOPK];
    if (tid == 0) {
#pragma unroll
        for (int k = 0; k < TOPK; k++) {
            int e = g_tok_e[t * 2 + k];
            int p = g_off[e] + atomicAdd(&g_cur[e], 1);
            spos[k] = p;
            g_tok_pos[t * 2 + k] = p;
        }
    }
    __syncthreads();
    float4 v = reinterpret_cast<const float4*>(X + (size_t)t * Dm)[tid];
    uint2 w = make_uint2(packh(v.x, v.y), packh(v.z, v.w));
#pragma unroll
    for (int k = 0; k < TOPK; k++)
        reinterpret_cast<uint2*>(g_XGh + (size_t)spos[k] * (Dm / 2))[tid] = w;
}

__global__ void k_aux_final(float* __restrict__ out)
{
    int tid = threadIdx.x;
    float imp[Ee];
#pragma unroll
    for (int e = 0; e < Ee; e++) imp[e] = 0.f;
    for (int t = tid; t < Ntok; t += 256)
#pragma unroll
        for (int e = 0; e < Ee; e++) imp[e] += g_auxp[t * Ee + e];
    float ld[Ee];
#pragma unroll
    for (int e = 0; e < Ee; e++) ld[e] = 0.f;
    for (int i = tid; i < Ntok * TOPK; i += 256) ld[g_auxi[i]] += 1.f;

    __shared__ float red[256 * Ee];
    __shared__ float simp[Ee];
#pragma unroll
    for (int e = 0; e < Ee; e++) red[tid * Ee + e] = imp[e];
    __syncthreads();
    for (int st = 128; st > 0; st >>= 1) {
        if (tid < st)
#pragma unroll
            for (int e = 0; e < Ee; e++)
                red[tid * Ee + e] += red[(tid + st) * Ee + e];
        __syncthreads();
    }
    if (tid == 0)
#pragma unroll
        for (int e = 0; e < Ee; e++) simp[e] = red[e];
    __syncthreads();
#pragma unroll
    for (int e = 0; e < Ee; e++) red[tid * Ee + e] = ld[e];
    __syncthreads();
    for (int st = 128; st > 0; st >>= 1) {
        if (tid < st)
#pragma unroll
            for (int e = 0; e < Ee; e++)
                red[tid * Ee + e] += red[(tid + st) * Ee + e];
        __syncthreads();
    }
    if (tid == 0) {
        float aux = 0.f;
#pragma unroll
        for (int e = 0; e < Ee; e++)
            aux += (simp[e] / (float)Ntok) * (red[e] / (float)(Ntok * TOPK));
        out[0] = (float)Ee * aux;
    }
}

// ---------------- host orchestration ----------------
extern "C" void kernel_launch(void* const* d_in, const int* in_sizes, int n_in,
                              void* d_out, int out_size)
{
    (void)in_sizes; (void)n_in;
    const float* x     = (const float*)d_in[0];
    const float* enc   = (const float*)d_in[1];
    const float* sa_wq = (const float*)d_in[2];
    const float* sa_bq = (const float*)d_in[3];
    const float* sa_wk = (const float*)d_in[4];
    const float* sa_bk = (const float*)d_in[5];
    const float* sa_wv = (const float*)d_in[6];
    const float* sa_bv = (const float*)d_in[7];
    const float* sa_wo = (const float*)d_in[8];
    const float* sa_bo = (const float*)d_in[9];
    const float* ca_wq = (const float*)d_in[10];
    const float* ca_bq = (const float*)d_in[11];
    const float* ca_wk = (const float*)d_in[12];
    const float* ca_bk = (const float*)d_in[13];
    const float* ca_wv = (const float*)d_in[14];
    const float* ca_bv = (const float*)d_in[15];
    const float* ca_wo = (const float*)d_in[16];
    const float* ca_bo = (const float*)d_in[17];
    const float* n1_g  = (const float*)d_in[18];
    const float* n1_b  = (const float*)d_in[19];
    const float* n2_g  = (const float*)d_in[20];
    const float* n2_b  = (const float*)d_in[21];
    const float* n3_g  = (const float*)d_in[22];
    const float* n3_b  = (const float*)d_in[23];
    const float* r_w   = (const float*)d_in[24];
    const float* r_b   = (const float*)d_in[25];
    const float* e_w1  = (const float*)d_in[26];
    const float* e_b1  = (const float*)d_in[27];
    const float* e_w2  = (const float*)d_in[28];
    const float* e_b2  = (const float*)d_in[29];

    void *pV, *pPR, *pX1, *pX2, *pYG;
    void *pQh, *pKh, *pxh, *pench, *pX1h, *pATh, *pwh, *pe1h, *pe2h, *pXGh, *pHBh;
    cudaGetSymbolAddress(&pV,  g_V);
    cudaGetSymbolAddress(&pPR, g_PR);
    cudaGetSymbolAddress(&pX1, g_X1);
    cudaGetSymbolAddress(&pX2, g_X2);
    cudaGetSymbolAddress(&pYG, g_YG);
    cudaGetSymbolAddress(&pQh,  g_Qh);
    cudaGetSymbolAddress(&pKh,  g_Kh);
    cudaGetSymbolAddress(&pxh,  g_xh);
    cudaGetSymbolAddress(&pench, g_ench);
    cudaGetSymbolAddress(&pX1h, g_X1h);
    cudaGetSymbolAddress(&pATh, g_ATh);
    cudaGetSymbolAddress(&pwh,  g_wh);
    cudaGetSymbolAddress(&pe1h, g_e1h);
    cudaGetSymbolAddress(&pe2h, g_e2h);
    cudaGetSymbolAddress(&pXGh, g_XGh);
    cudaGetSymbolAddress(&pHBh, g_HBh);
    float* V  = (float*)pV;
    float* PR = (float*)pPR; float* X1 = (float*)pX1; float* X2 = (float*)pX2;
    float* YG = (float*)pYG;
    unsigned* Qh   = (unsigned*)pQh;
    unsigned* Kh   = (unsigned*)pKh;
    unsigned* xh   = (unsigned*)pxh;
    unsigned* ench = (unsigned*)pench;
    unsigned* X1h  = (unsigned*)pX1h;
    unsigned* ATh  = (unsigned*)pATh;
    unsigned* wh   = (unsigned*)pwh;
    unsigned* e1h  = (unsigned*)pe1h;
    unsigned* e2h  = (unsigned*)pe2h;
    unsigned* XGh  = (unsigned*)pXGh;
    unsigned* HBh  = (unsigned*)pHBh;
    float* out = (float*)d_out;

    static int smem_set = 0;
    if (!smem_set) {
        cudaFuncSetAttribute(k_flash, cudaFuncAttributeMaxDynamicSharedMemorySize, FLASH_SMEM);
        cudaFuncSetAttribute(k_gemm_h, cudaFuncAttributeMaxDynamicSharedMemorySize, H_SMEM);
        cudaFuncSetAttribute(k_moe_gemm_h, cudaFuncAttributeMaxDynamicSharedMemorySize, H_SMEM);
        smem_set = 1;
    }

    dim3 gblk(128);
    dim3 blk(256);
    dim3 gProj(Ntok / 128, Dm / 128);
    dim3 gFlash(Sseq / QT, Bbat * Hh);
    const int WSTRIDE = (Dm / 2) * Dm;

    // ---- fp16 conversions ----
    {
        int nq = Ntok * Dm / 4;
        k_cvtA<<<(nq + 255) / 256, 256>>>(x, xh, nq);
        k_cvtA<<<(nq + 255) / 256, 256>>>(enc, ench, nq);
        dim3 gw1(Dm / 64, Dm / 64, 1);
        k_cvtBT<<<gw1, 256>>>(sa_wq, wh + 0 * WSTRIDE, Dm, Dm);
        k_cvtBT<<<gw1, 256>>>(sa_wk, wh + 1 * WSTRIDE, Dm, Dm);
        k_cvtBT<<<gw1, 256>>>(sa_wv, wh + 2 * WSTRIDE, Dm, Dm);
        k_cvtBT<<<gw1, 256>>>(sa_wo, wh + 3 * WSTRIDE, Dm, Dm);
        k_cvtBT<<<gw1, 256>>>(ca_wq, wh + 4 * WSTRIDE, Dm, Dm);
        k_cvtBT<<<gw1, 256>>>(ca_wk, wh + 5 * WSTRIDE, Dm, Dm);
        k_cvtBT<<<gw1, 256>>>(ca_wv, wh + 6 * WSTRIDE, Dm, Dm);
        k_cvtBT<<<gw1, 256>>>(ca_wo, wh + 7 * WSTRIDE, Dm, Dm);
        dim3 ge1(Dm / 64, Ff / 64, Ee);
        k_cvtBT<<<ge1, 256>>>(e_w1, e1h, Dm, Ff);
        dim3 ge2(Ff / 64, Dm / 64, Ee);
        k_cvtBT<<<ge2, 256>>>(e_w2, e2h, Ff, Dm);
    }

    // ---- self attention (Q,K emitted fp16; V f32) ----
    k_gemm_h<<<gProj, gblk, H_SMEM>>>(xh, Dm/2, wh + 0*WSTRIDE, Dm/2, sa_bq, (float*)0, Qh, Dm, Ntok, Dm, 0);
    k_gemm_h<<<gProj, gblk, H_SMEM>>>(xh, Dm/2, wh + 1*WSTRIDE, Dm/2, sa_bk, (float*)0, Kh, Dm, Ntok, Dm, 0);
    k_gemm_h<<<gProj, gblk, H_SMEM>>>(xh, Dm/2, wh + 2*WSTRIDE, Dm/2, sa_bv, V, (unsigned*)0, Dm, Ntok, Dm, 0);
    k_flash<<<gFlash, blk, FLASH_SMEM>>>(Qh, Kh, V, ATh);
    k_gemm_h<<<gProj, gblk, H_SMEM>>>(ATh, Dm/2, wh + 3*WSTRIDE, Dm/2, sa_bo, PR, (unsigned*)0, Dm, Ntok, Dm, 0);
    k_ln_res<<<Ntok, blk>>>(x, PR, n1_g, n1_b, X1, X1h);

    // ---- cross attention ----
    k_gemm_h<<<gProj, gblk, H_SMEM>>>(X1h,  Dm/2, wh + 4*WSTRIDE, Dm/2, ca_bq, (float*)0, Qh, Dm, Ntok, Dm, 0);
    k_gemm_h<<<gProj, gblk, H_SMEM>>>(ench, Dm/2, wh + 5*WSTRIDE, Dm/2, ca_bk, (float*)0, Kh, Dm, Ntok, Dm, 0);
    k_gemm_h<<<gProj, gblk, H_SMEM>>>(ench, Dm/2, wh + 6*WSTRIDE, Dm/2, ca_bv, V, (unsigned*)0, Dm, Ntok, Dm, 0);
    k_flash<<<gFlash, blk, FLASH_SMEM>>>(Qh, Kh, V, ATh);
    k_gemm_h<<<gProj, gblk, H_SMEM>>>(ATh, Dm/2, wh + 7*WSTRIDE, Dm/2, ca_bo, PR, (unsigned*)0, Dm, Ntok, Dm, 0);
    k_ln_res<<<Ntok, blk>>>(X1, PR, n2_g, n2_b, X2, (unsigned*)0);

    // ---- MoE (sparse top-2 dispatch) ----
    k_moe_init<<<1, blk>>>();
    k_router<<<Ntok, blk>>>(X2, r_w, r_b, 0);
    k_offsets<<<1, 1>>>();
    k_gather<<<Ntok, blk>>>(X2);
    k_moe_gemm_h<<<dim3(Ntok / 128, Ff / 128, Ee), gblk, H_SMEM>>>(XGh, e1h, e_b1, (float*)0, HBh, Dm, Ff, 1);
    k_moe_gemm_h<<<dim3(Ntok / 128, Dm / 128, Ee), gblk, H_SMEM>>>(HBh, e2h, e_b2, YG, (unsigned*)0, Ff, Dm, 0);
    k_moe_out<<<Ntok, blk>>>(X2, n3_g, n3_b, out);

    // ---- aux loss (router recompute on OUTPUT, per reference) ----
    if (out_size > Ntok * Dm) {
        k_router<<<Ntok, blk>>>(out, r_w, r_b, 1);
        k_aux_final<<<1, blk>>>(out + (out_size - 1));
    }
}